// round 9
// baseline (speedup 1.0000x reference)
#include <cuda_runtime.h>
#include <cuda_fp16.h>
#include <math.h>

#define H 128
#define S 64
#define PRED 50
#define BT 16
#define NBLK 128
#define NTHR 512

// ---------------- fragment-ordered weights, GATE-INTERLEAVED columns ----------------
// Fragment tile nt of warp w=nt/NTg holds gate (nt%NTg), j = w*8+gid, so each thread's
// C fragment carries all gates for its (row, j) pair -> in-register combine.
__device__ __align__(16) __half g_wf_l0[64 * 9 * 128];    // LSTM L0: K=144 (128 h + 4 x + pad)
__device__ __align__(16) __half g_wf_l1[64 * 16 * 128];   // LSTM L1: K=256 (wih1|whh1)
__device__ __align__(16) __half g_wf_gi0[48 * 8 * 128];   // GRU: K=128
__device__ __align__(16) __half g_wf_gh0[48 * 8 * 128];
__device__ __align__(16) __half g_wf_gi1[48 * 8 * 128];
__device__ __align__(16) __half g_wf_gh1[48 * 8 * 128];
__device__ __align__(16) __half g_wf_br[16 * 8 * 128];    // bridge: natural order
__device__ __align__(16) float  g_b0[512];                // natural order n = g*128+j
__device__ __align__(16) float  g_b1[512];
__device__ __align__(16) float  g_bgi0[384];
__device__ __align__(16) float  g_bgh0[384];
__device__ __align__(16) float  g_bgi1[384];
__device__ __align__(16) float  g_bgh1[384];
__device__ __align__(16) float  g_wfc1[128 * 64];         // [k][c] fp32

__global__ void prep_kernel(
    const float* __restrict__ lwih0, const float* __restrict__ lwhh0,
    const float* __restrict__ lbih0, const float* __restrict__ lbhh0,
    const float* __restrict__ lwih1, const float* __restrict__ lwhh1,
    const float* __restrict__ lbih1, const float* __restrict__ lbhh1,
    const float* __restrict__ gwi0, const float* __restrict__ gwh0,
    const float* __restrict__ gbi0, const float* __restrict__ gbh0,
    const float* __restrict__ gwi1, const float* __restrict__ gwh1,
    const float* __restrict__ gbi1, const float* __restrict__ gbh1,
    const float* __restrict__ brw, const float* __restrict__ fc1w)
{
    int i0 = blockIdx.x * blockDim.x + threadIdx.x;
    int st = gridDim.x * blockDim.x;

    // decode i -> (nt, s, lane, e), then k within K
#define FRAG_DECODE(i, KS)                                  \
    int e = (i) & 3;                                        \
    int lane = ((i) >> 2) & 31;                             \
    int q2 = (i) >> 7;                                      \
    int s = q2 % (KS);                                      \
    int nt = q2 / (KS);                                     \
    int gid = lane >> 2;                                    \
    int k = s * 16 + (lane & 3) * 2 + (e & 1) + (e >> 1) * 8;

    for (int i = i0; i < 64 * 9 * 128; i += st) {
        FRAG_DECODE(i, 9);
        int n = (nt & 3) * 128 + (nt >> 2) * 8 + gid;   // gate-interleaved
        float v = 0.f;
        if (k < 128)      v = lwhh0[n * 128 + k];
        else if (k < 132) v = lwih0[n * 4 + (k - 128)];
        g_wf_l0[i] = __float2half(v);
    }
    for (int i = i0; i < 64 * 16 * 128; i += st) {
        FRAG_DECODE(i, 16);
        int n = (nt & 3) * 128 + (nt >> 2) * 8 + gid;
        float v = (k < 128) ? lwih1[n * 128 + k] : lwhh1[n * 128 + (k - 128)];
        g_wf_l1[i] = __float2half(v);
    }
    for (int i = i0; i < 48 * 8 * 128; i += st) {
        FRAG_DECODE(i, 8);
        int n = (nt % 3) * 128 + (nt / 3) * 8 + gid;
        g_wf_gi0[i] = __float2half(gwi0[n * 128 + k]);
        g_wf_gh0[i] = __float2half(gwh0[n * 128 + k]);
        g_wf_gi1[i] = __float2half(gwi1[n * 128 + k]);
        g_wf_gh1[i] = __float2half(gwh1[n * 128 + k]);
    }
    for (int i = i0; i < 16 * 8 * 128; i += st) {
        FRAG_DECODE(i, 8);
        int n = nt * 8 + gid;                            // natural (no gates)
        g_wf_br[i] = __float2half(brw[n * 128 + k]);
    }
#undef FRAG_DECODE
    for (int i = i0; i < 512; i += st) {
        g_b0[i] = lbih0[i] + lbhh0[i];
        g_b1[i] = lbih1[i] + lbhh1[i];
    }
    for (int i = i0; i < 384; i += st) {
        g_bgi0[i] = gbi0[i]; g_bgh0[i] = gbh0[i];
        g_bgi1[i] = gbi1[i]; g_bgh1[i] = gbh1[i];
    }
    for (int i = i0; i < 128 * 64; i += st) {
        int k = i / 64, c = i % 64;
        g_wfc1[i] = fc1w[c * 128 + k];
    }
}

__device__ __forceinline__ float sigm(float v) { return 1.f / (1.f + __expf(-v)); }

__device__ __forceinline__ unsigned smem_u32(const void* p) {
    return (unsigned)__cvta_generic_to_shared(p);
}
__device__ __forceinline__ void ldsm_x4(unsigned addr, unsigned& r0, unsigned& r1,
                                        unsigned& r2, unsigned& r3) {
    asm volatile("ldmatrix.sync.aligned.m8n8.x4.shared.b16 {%0,%1,%2,%3}, [%4];\n"
                 : "=r"(r0), "=r"(r1), "=r"(r2), "=r"(r3) : "r"(addr));
}
__device__ __forceinline__ void hmma(float* c, unsigned a0, unsigned a1, unsigned a2,
                                     unsigned a3, unsigned b0, unsigned b1) {
    asm volatile("mma.sync.aligned.m16n8k16.row.col.f32.f16.f16.f32 "
                 "{%0,%1,%2,%3}, {%4,%5,%6,%7}, {%8,%9}, {%0,%1,%2,%3};\n"
                 : "+f"(c[0]), "+f"(c[1]), "+f"(c[2]), "+f"(c[3])
                 : "r"(a0), "r"(a1), "r"(a2), "r"(a3), "r"(b0), "r"(b1));
}

// Warp GEMM, accumulators stay in registers: c[tile][rs*2+e] = rows {gid, gid+8}, cols {2tig, 2tig+1}
template<int NT, int KS>
__device__ __forceinline__ void hgemm_reg(const __half* A, int astr,
                                          const __half* __restrict__ WF,
                                          int ntile0, float (&c)[NT][4])
{
    const int lane = threadIdx.x & 31;
    unsigned abase = smem_u32(A) + (unsigned)(((lane & 15) * astr + ((lane >> 4) << 3)) * 2);
#pragma unroll
    for (int i = 0; i < NT; i++) { c[i][0] = c[i][1] = c[i][2] = c[i][3] = 0.f; }
#pragma unroll
    for (int s = 0; s < KS; s++) {
        unsigned a0, a1, a2, a3;
        ldsm_x4(abase + s * 32, a0, a1, a2, a3);
#pragma unroll
        for (int i = 0; i < NT; i++) {
            uint2 b = *(const uint2*)(WF + (((size_t)(ntile0 + i) * KS + s) * 32 + lane) * 4);
            hmma(c[i], a0, a1, a2, a3, b.x, b.y);
        }
    }
}

// Legacy smem-output variant (bridge only)
template<int NT, int KS>
__device__ __forceinline__ void hgemm(const __half* A, int astr,
                                      const __half* __restrict__ WF,
                                      int ntile0, float* outp, int ostr)
{
    float c[NT][4];
    hgemm_reg<NT, KS>(A, astr, WF, ntile0, c);
    const int lane = threadIdx.x & 31;
    const int gid = lane >> 2, tig = lane & 3;
#pragma unroll
    for (int i = 0; i < NT; i++) {
        int n = (ntile0 + i) * 8 + tig * 2;
        *(float2*)(outp + gid * ostr + n) = make_float2(c[i][0], c[i][1]);
        *(float2*)(outp + (gid + 8) * ostr + n) = make_float2(c[i][2], c[i][3]);
    }
}

// smem strides (halves); rows 16B-aligned, odd multiples of 16B -> LDSM conflict-free
#define STR_A  152
#define STR_B  264
#define STR_D  136
#define GST    520

__global__ void __launch_bounds__(NTHR, 1) rnn_kernel(
    const float* __restrict__ x,
    const float* __restrict__ brb, const float* __restrict__ fc1b,
    const float* __restrict__ fc2w, const float* __restrict__ fc2b,
    float* __restrict__ out)
{
    extern __shared__ char smraw[];
    __half* xs   = (__half*)smraw;                 // 8192 B
    __half* bufA = (__half*)(smraw + 8192);        // [2][16][152]  9728 B
    __half* bufB = (__half*)(smraw + 17920);       // [2][16][264] 16896 B
    __half* d0b  = (__half*)(smraw + 34816);       // [2][16][136]  8704 B
    __half* d1b  = (__half*)(smraw + 43520);       // [2][16][136]  8704 B
    float*  gbuf = (float*)(smraw + 52224);        // [16][520]    33280 B (bridge only)
    float*  fcz  = (float*)(smraw + 85504);        // [16][64]      4096 B

    const int tid = threadIdx.x;
    const int wid = tid >> 5;
    const int lane = tid & 31;
    const int gid = lane >> 2, tig = lane & 3;
    const int j0 = wid * 8 + tig * 2;              // this thread's 2 columns (j0, j0+1)
    const int b0 = blockIdx.x * BT;

    // init: x tile, zero buffers, x_0 into bufA[0]
    for (int i = tid; i < BT * 256; i += NTHR) {
        int r = i >> 8, q = i & 255;
        xs[i] = __float2half(x[(size_t)(b0 + r) * 256 + q]);
    }
    for (int i = tid; i < 2 * 16 * STR_A; i += NTHR) bufA[i] = __float2half(0.f);
    for (int i = tid; i < 2 * 16 * STR_B; i += NTHR) bufB[i] = __float2half(0.f);
    if (tid < 64) {
        int r = tid >> 2, k = tid & 3;
        bufA[r * STR_A + 128 + k] = __float2half(x[(size_t)(b0 + r) * 256 + k]);
    }
    // per-thread bias registers (constant across t)
    float b0r[4][2], b1r[4][2];
#pragma unroll
    for (int g = 0; g < 4; g++)
#pragma unroll
        for (int e = 0; e < 2; e++) {
            b0r[g][e] = g_b0[g * 128 + j0 + e];
            b1r[g][e] = g_b1[g * 128 + j0 + e];
        }
    float c0st[2][2] = {{0.f, 0.f}, {0.f, 0.f}};
    float c1st[2][2] = {{0.f, 0.f}, {0.f, 0.f}};
    __syncthreads();

    // ---------------- LSTM encoder: 2 syncs per timestep ----------------
    for (int t = 0; t < S; t++) {
        const int p = t & 1, np = p ^ 1;
        __half* A0  = bufA + p * 16 * STR_A;
        __half* A0n = bufA + np * 16 * STR_A;
        __half* Bp  = bufB + p * 16 * STR_B;
        __half* Bn  = bufB + np * 16 * STR_B;

        // phase 1: L0 GEMM + in-register combine
        {
            float c4[4][4];
            hgemm_reg<4, 9>(A0, STR_A, g_wf_l0, wid * 4, c4);
            float hh[2][2];
#pragma unroll
            for (int rs = 0; rs < 2; rs++)
#pragma unroll
                for (int e = 0; e < 2; e++) {
                    int ix = rs * 2 + e;
                    float ii = c4[0][ix] + b0r[0][e];
                    float ff = c4[1][ix] + b0r[1][e];
                    float gg = c4[2][ix] + b0r[2][e];
                    float oo = c4[3][ix] + b0r[3][e];
                    float cc = sigm(ff) * c0st[rs][e] + sigm(ii) * tanhf(gg);
                    c0st[rs][e] = cc;
                    hh[rs][e] = sigm(oo) * tanhf(cc);
                }
            __half2 h0v = __floats2half2_rn(hh[0][0], hh[0][1]);
            __half2 h1v = __floats2half2_rn(hh[1][0], hh[1][1]);
            *(__half2*)(A0n + gid * STR_A + j0) = h0v;
            *(__half2*)(A0n + (gid + 8) * STR_A + j0) = h1v;
            *(__half2*)(Bp + gid * STR_B + j0) = h0v;
            *(__half2*)(Bp + (gid + 8) * STR_B + j0) = h1v;
            if (t < S - 1 && tid < 64) {
                int r = tid >> 2, k = tid & 3;
                A0n[r * STR_A + 128 + k] = xs[r * 256 + (t + 1) * 4 + k];
            }
        }
        __syncthreads();

        // phase 2: L1 GEMM (concat-K) + combine
        {
            float c4[4][4];
            hgemm_reg<4, 16>(Bp, STR_B, g_wf_l1, wid * 4, c4);
            float hh[2][2];
#pragma unroll
            for (int rs = 0; rs < 2; rs++)
#pragma unroll
                for (int e = 0; e < 2; e++) {
                    int ix = rs * 2 + e;
                    float ii = c4[0][ix] + b1r[0][e];
                    float ff = c4[1][ix] + b1r[1][e];
                    float gg = c4[2][ix] + b1r[2][e];
                    float oo = c4[3][ix] + b1r[3][e];
                    float cc = sigm(ff) * c1st[rs][e] + sigm(ii) * tanhf(gg);
                    c1st[rs][e] = cc;
                    hh[rs][e] = sigm(oo) * tanhf(cc);
                }
            *(__half2*)(Bn + gid * STR_B + 128 + j0) = __floats2half2_rn(hh[0][0], hh[0][1]);
            *(__half2*)(Bn + (gid + 8) * STR_B + 128 + j0) = __floats2half2_rn(hh[1][0], hh[1][1]);
        }
        __syncthreads();
    }
    __half* h0f = bufA;           // final h0 (buffer 0)
    __half* h1f = bufB + 128;     // final h1 (buffer 0, cols 128-255)

    // ---------------- bridge (one-off, via smem) ----------------
    if (wid < 8) hgemm<2, 8>(h0f, STR_A, g_wf_br, wid * 2, gbuf, GST);
    else         hgemm<2, 8>(h1f, STR_B, g_wf_br, (wid - 8) * 2, gbuf + 128, GST);
    __syncthreads();
#pragma unroll
    for (int it = 0; it < 4; it++) {
        int idx = tid + it * NTHR;
        int r = idx >> 7, j = idx & 127;
        float bv = brb[j];
        d0b[r * STR_D + j] = __float2half(tanhf(gbuf[r * GST + j] + bv));
        d1b[r * STR_D + j] = __float2half(tanhf(gbuf[r * GST + 128 + j] + bv));
    }
    __syncthreads();

    // per-thread GRU state + bias registers
    float d0st[2][2], d1st[2][2];
#pragma unroll
    for (int rs = 0; rs < 2; rs++)
#pragma unroll
        for (int e = 0; e < 2; e++) {
            d0st[rs][e] = __half2float(d0b[(gid + rs * 8) * STR_D + j0 + e]);
            d1st[rs][e] = __half2float(d1b[(gid + rs * 8) * STR_D + j0 + e]);
        }
    float bgi0r[3][2], bgh0r[3][2], bgi1r[3][2], bgh1r[3][2];
#pragma unroll
    for (int g = 0; g < 3; g++)
#pragma unroll
        for (int e = 0; e < 2; e++) {
            bgi0r[g][e] = g_bgi0[g * 128 + j0 + e];
            bgh0r[g][e] = g_bgh0[g * 128 + j0 + e];
            bgi1r[g][e] = g_bgi1[g * 128 + j0 + e];
            bgh1r[g][e] = g_bgh1[g * 128 + j0 + e];
        }

    // ---------------- autoregressive GRU decode, head folded ----------------
    for (int t = 0; t < PRED; t++) {
        const int pg = t & 1, npg = pg ^ 1;
        __half* d0p = d0b + pg * 16 * STR_D;
        __half* d0n = d0b + npg * 16 * STR_D;
        __half* d1p = d1b + pg * 16 * STR_D;
        __half* d1n = d1b + npg * 16 * STR_D;
        const __half* A1 = (t == 0) ? h1f : d1p;
        const int a1str = (t == 0) ? STR_B : STR_D;

        // phase A: GRU L0 (+ fc1 of step t-1)
        {
            float ai[3][4], ah[3][4];
            hgemm_reg<3, 8>(A1, a1str, g_wf_gi0, wid * 3, ai);
            hgemm_reg<3, 8>(d0p, STR_D, g_wf_gh0, wid * 3, ah);
#pragma unroll
            for (int rs = 0; rs < 2; rs++)
#pragma unroll
                for (int e = 0; e < 2; e++) {
                    int ix = rs * 2 + e;
                    float rr = sigm(ai[0][ix] + bgi0r[0][e] + ah[0][ix] + bgh0r[0][e]);
                    float zz = sigm(ai[1][ix] + bgi0r[1][e] + ah[1][ix] + bgh0r[1][e]);
                    float nn = tanhf(ai[2][ix] + bgi0r[2][e] + rr * (ah[2][ix] + bgh0r[2][e]));
                    d0st[rs][e] = (1.f - zz) * nn + zz * d0st[rs][e];
                }
            *(__half2*)(d0n + gid * STR_D + j0) = __floats2half2_rn(d0st[0][0], d0st[0][1]);
            *(__half2*)(d0n + (gid + 8) * STR_D + j0) = __floats2half2_rn(d0st[1][0], d0st[1][1]);
        }
        if (t > 0) {   // fc1 for step t-1, input d1p
#pragma unroll
            for (int half = 0; half < 2; half++) {
                int o = tid + half * NTHR;
                int r = o >> 6, c = o & 63;
                float acc = fc1b[c];
#pragma unroll 4
                for (int k = 0; k < 128; k += 2) {
                    float2 fv = __half22float2(*(const __half2*)(d1p + r * STR_D + k));
                    acc = fmaf(fv.x, g_wfc1[(k + 0) * 64 + c], acc);
                    acc = fmaf(fv.y, g_wfc1[(k + 1) * 64 + c], acc);
                }
                fcz[r * 64 + c] = fmaxf(acc, 0.f);
            }
        }
        __syncthreads();

        // phase B: GRU L1 (+ fc2 of step t-1)
        {
            float ai[3][4], ah[3][4];
            hgemm_reg<3, 8>(d0n, STR_D, g_wf_gi1, wid * 3, ai);
            hgemm_reg<3, 8>(d1p, STR_D, g_wf_gh1, wid * 3, ah);
#pragma unroll
            for (int rs = 0; rs < 2; rs++)
#pragma unroll
                for (int e = 0; e < 2; e++) {
                    int ix = rs * 2 + e;
                    float rr = sigm(ai[0][ix] + bgi1r[0][e] + ah[0][ix] + bgh1r[0][e]);
                    float zz = sigm(ai[1][ix] + bgi1r[1][e] + ah[1][ix] + bgh1r[1][e]);
                    float nn = tanhf(ai[2][ix] + bgi1r[2][e] + rr * (ah[2][ix] + bgh1r[2][e]));
                    d1st[rs][e] = (1.f - zz) * nn + zz * d1st[rs][e];
                }
            *(__half2*)(d1n + gid * STR_D + j0) = __floats2half2_rn(d1st[0][0], d1st[0][1]);
            *(__half2*)(d1n + (gid + 8) * STR_D + j0) = __floats2half2_rn(d1st[1][0], d1st[1][1]);
        }
        if (t > 0 && tid < 32) {   // fc2 for step t-1
            int r = tid >> 1, cc = tid & 1;
            float s = fc2b[cc];
#pragma unroll
            for (int k = 0; k < 64; k++)
                s = fmaf(fcz[r * 64 + k], fc2w[cc * 64 + k], s);
            out[(size_t)(b0 + r) * PRED * 2 + (t - 1) * 2 + cc] = s;
        }
        __syncthreads();
    }

    // ---------------- tail: head for t = PRED-1 (final d1 in buffer 0) ----------------
    {
        const __half* d1last = d1b;
#pragma unroll
        for (int half = 0; half < 2; half++) {
            int o = tid + half * NTHR;
            int r = o >> 6, c = o & 63;
            float acc = fc1b[c];
#pragma unroll 4
            for (int k = 0; k < 128; k += 2) {
                float2 fv = __half22float2(*(const __half2*)(d1last + r * STR_D + k));
                acc = fmaf(fv.x, g_wfc1[(k + 0) * 64 + c], acc);
                acc = fmaf(fv.y, g_wfc1[(k + 1) * 64 + c], acc);
            }
            fcz[r * 64 + c] = fmaxf(acc, 0.f);
        }
        __syncthreads();
        if (tid < 32) {
            int r = tid >> 1, cc = tid & 1;
            float s = fc2b[cc];
#pragma unroll
            for (int k = 0; k < 64; k++)
                s = fmaf(fcz[r * 64 + k], fc2w[cc * 64 + k], s);
            out[(size_t)(b0 + r) * PRED * 2 + (PRED - 1) * 2 + cc] = s;
        }
    }
}

extern "C" void kernel_launch(void* const* d_in, const int* in_sizes, int n_in,
                              void* d_out, int out_size)
{
    const float* p[24];
    int np = 0;
    for (int i = 0; i < n_in && np < 24; i++) {
        if (in_sizes[i] == 1) continue;
        p[np++] = (const float*)d_in[i];
    }
    const float* x = p[0];
    const float *lwih0 = p[1], *lwhh0 = p[2], *lbih0 = p[3], *lbhh0 = p[4];
    const float *lwih1 = p[5], *lwhh1 = p[6], *lbih1 = p[7], *lbhh1 = p[8];
    const float *gwi0 = p[9], *gwh0 = p[10], *gbi0 = p[11], *gbh0 = p[12];
    const float *gwi1 = p[13], *gwh1 = p[14], *gbi1 = p[15], *gbh1 = p[16];
    const float *brw = p[17], *brb = p[18];
    const float *fc1w = p[19], *fc1b = p[20];
    const float *fc2w = p[21], *fc2b = p[22];

    prep_kernel<<<512, 256>>>(lwih0, lwhh0, lbih0, lbhh0, lwih1, lwhh1, lbih1, lbhh1,
                              gwi0, gwh0, gbi0, gbh0, gwi1, gwh1, gbi1, gbh1,
                              brw, fc1w);

    const int smem = 89600;
    cudaFuncSetAttribute(rnn_kernel, cudaFuncAttributeMaxDynamicSharedMemorySize, smem);
    rnn_kernel<<<NBLK, NTHR, smem>>>(x, brb, fc1b, fc2w, fc2b, (float*)d_out);
}

// round 10
// speedup vs baseline: 1.3640x; 1.3640x over previous
#include <cuda_runtime.h>
#include <cuda_fp16.h>
#include <math.h>

#define H 128
#define S 64
#define PRED 50
#define BT 16
#define NBLK 128
#define NTHR 512

// ---------------- fragment-ordered weights: [ntile][kstep][lane][4 halves] ----------------
__device__ __align__(16) __half g_wf_l0[64 * 9 * 128];    // LSTM L0: K=144 (128 h + 4 x + pad)
__device__ __align__(16) __half g_wf_l1[64 * 16 * 128];   // LSTM L1: K=256 (wih1|whh1)
__device__ __align__(16) __half g_wf_gi0[48 * 8 * 128];   // GRU: K=128
__device__ __align__(16) __half g_wf_gh0[48 * 8 * 128];
__device__ __align__(16) __half g_wf_gi1[48 * 8 * 128];
__device__ __align__(16) __half g_wf_gh1[48 * 8 * 128];
__device__ __align__(16) __half g_wf_br[16 * 8 * 128];    // bridge
__device__ __align__(16) float  g_b0[512];                // natural order n = g*128+j
__device__ __align__(16) float  g_b1[512];
__device__ __align__(16) float  g_bgi0[384];
__device__ __align__(16) float  g_bgh0[384];
__device__ __align__(16) float  g_bgi1[384];
__device__ __align__(16) float  g_bgh1[384];
__device__ __align__(16) float  g_wfc1[128 * 64];         // [k][c] fp32

__global__ void prep_kernel(
    const float* __restrict__ lwih0, const float* __restrict__ lwhh0,
    const float* __restrict__ lbih0, const float* __restrict__ lbhh0,
    const float* __restrict__ lwih1, const float* __restrict__ lwhh1,
    const float* __restrict__ lbih1, const float* __restrict__ lbhh1,
    const float* __restrict__ gwi0, const float* __restrict__ gwh0,
    const float* __restrict__ gbi0, const float* __restrict__ gbh0,
    const float* __restrict__ gwi1, const float* __restrict__ gwh1,
    const float* __restrict__ gbi1, const float* __restrict__ gbh1,
    const float* __restrict__ brw, const float* __restrict__ fc1w)
{
    int i0 = blockIdx.x * blockDim.x + threadIdx.x;
    int st = gridDim.x * blockDim.x;

#define FRAG_DECODE(i, KS)                                  \
    int e = (i) & 3;                                        \
    int lane = ((i) >> 2) & 31;                             \
    int q2 = (i) >> 7;                                      \
    int s = q2 % (KS);                                      \
    int nt = q2 / (KS);                                     \
    int n = nt * 8 + (lane >> 2);                           \
    int k = s * 16 + (lane & 3) * 2 + (e & 1) + (e >> 1) * 8;

    for (int i = i0; i < 64 * 9 * 128; i += st) {
        FRAG_DECODE(i, 9);
        float v = 0.f;
        if (k < 128)      v = lwhh0[n * 128 + k];
        else if (k < 132) v = lwih0[n * 4 + (k - 128)];
        g_wf_l0[i] = __float2half(v);
    }
    for (int i = i0; i < 64 * 16 * 128; i += st) {
        FRAG_DECODE(i, 16);
        float v = (k < 128) ? lwih1[n * 128 + k] : lwhh1[n * 128 + (k - 128)];
        g_wf_l1[i] = __float2half(v);
    }
    for (int i = i0; i < 48 * 8 * 128; i += st) {
        FRAG_DECODE(i, 8);
        g_wf_gi0[i] = __float2half(gwi0[n * 128 + k]);
        g_wf_gh0[i] = __float2half(gwh0[n * 128 + k]);
        g_wf_gi1[i] = __float2half(gwi1[n * 128 + k]);
        g_wf_gh1[i] = __float2half(gwh1[n * 128 + k]);
    }
    for (int i = i0; i < 16 * 8 * 128; i += st) {
        FRAG_DECODE(i, 8);
        g_wf_br[i] = __float2half(brw[n * 128 + k]);
    }
#undef FRAG_DECODE
    for (int i = i0; i < 512; i += st) {
        g_b0[i] = lbih0[i] + lbhh0[i];
        g_b1[i] = lbih1[i] + lbhh1[i];
    }
    for (int i = i0; i < 384; i += st) {
        g_bgi0[i] = gbi0[i]; g_bgh0[i] = gbh0[i];
        g_bgi1[i] = gbi1[i]; g_bgh1[i] = gbh1[i];
    }
    for (int i = i0; i < 128 * 64; i += st) {
        int k = i / 64, c = i % 64;
        g_wfc1[i] = fc1w[c * 128 + k];
    }
}

__device__ __forceinline__ float sigm(float v) { return 1.f / (1.f + __expf(-v)); }

__device__ __forceinline__ unsigned smem_u32(const void* p) {
    return (unsigned)__cvta_generic_to_shared(p);
}
__device__ __forceinline__ void ldsm_x4(unsigned addr, unsigned& r0, unsigned& r1,
                                        unsigned& r2, unsigned& r3) {
    asm volatile("ldmatrix.sync.aligned.m8n8.x4.shared.b16 {%0,%1,%2,%3}, [%4];\n"
                 : "=r"(r0), "=r"(r1), "=r"(r2), "=r"(r3) : "r"(addr));
}
__device__ __forceinline__ void hmma(float* c, unsigned a0, unsigned a1, unsigned a2,
                                     unsigned a3, unsigned b0, unsigned b1) {
    asm volatile("mma.sync.aligned.m16n8k16.row.col.f32.f16.f16.f32 "
                 "{%0,%1,%2,%3}, {%4,%5,%6,%7}, {%8,%9}, {%0,%1,%2,%3};\n"
                 : "+f"(c[0]), "+f"(c[1]), "+f"(c[2]), "+f"(c[3])
                 : "r"(a0), "r"(a1), "r"(a2), "r"(a3), "r"(b0), "r"(b1));
}

// Warp GEMM: C[16 x NT*8] = A[16 x KS*16] @ W, C -> smem fp32 (R7-proven mapping).
template<int NT, int KS>
__device__ __forceinline__ void hgemm(const __half* A, int astr,
                                      const __half* __restrict__ WF,
                                      int ntile0, float* outp, int ostr)
{
    const int lane = threadIdx.x & 31;
    unsigned abase = smem_u32(A) + (unsigned)(((lane & 15) * astr + ((lane >> 4) << 3)) * 2);
    float c[NT][4];
#pragma unroll
    for (int i = 0; i < NT; i++) { c[i][0] = c[i][1] = c[i][2] = c[i][3] = 0.f; }
#pragma unroll
    for (int s = 0; s < KS; s++) {
        unsigned a0, a1, a2, a3;
        ldsm_x4(abase + s * 32, a0, a1, a2, a3);
#pragma unroll
        for (int i = 0; i < NT; i++) {
            uint2 b = *(const uint2*)(WF + (((size_t)(ntile0 + i) * KS + s) * 32 + lane) * 4);
            hmma(c[i], a0, a1, a2, a3, b.x, b.y);
        }
    }
    const int gid = lane >> 2, tig = lane & 3;
#pragma unroll
    for (int i = 0; i < NT; i++) {
        int n = (ntile0 + i) * 8 + tig * 2;
        *(float2*)(outp + gid * ostr + n) = make_float2(c[i][0], c[i][1]);
        *(float2*)(outp + (gid + 8) * ostr + n) = make_float2(c[i][2], c[i][3]);
    }
}

#define STR_A  152
#define STR_B  264
#define STR_D  136
#define GST    520
#define GSTG   392

__global__ void __launch_bounds__(NTHR, 1) rnn_kernel(
    const float* __restrict__ x,
    const float* __restrict__ brb, const float* __restrict__ fc1b,
    const float* __restrict__ fc2w, const float* __restrict__ fc2b,
    float* __restrict__ out)
{
    extern __shared__ char smraw[];
    __half* xs   = (__half*)smraw;                 //  8192 B
    __half* bufA = (__half*)(smraw + 8192);        // [2][16][152]   9728 B
    __half* bufB = (__half*)(smraw + 17920);       // [2][16][264]  16896 B
    __half* d0b  = (__half*)(smraw + 34816);       // [2][16][136]   8704 B
    __half* d1b  = (__half*)(smraw + 43520);       // [2][16][136]   8704 B
    float*  gbuf = (float*)(smraw + 52224);        // 2x[16][520]   66560 B
    float*  fcz  = (float*)(smraw + 118784);       // [16][64]       4096 B

    const int tid = threadIdx.x;
    const int wid = tid >> 5;
    const int b0 = blockIdx.x * BT;

    // init
    for (int i = tid; i < BT * 256; i += NTHR) {
        int r = i >> 8, q = i & 255;
        xs[i] = __float2half(x[(size_t)(b0 + r) * 256 + q]);
    }
    for (int i = tid; i < 2 * 16 * STR_A; i += NTHR) bufA[i] = __float2half(0.f);
    for (int i = tid; i < 2 * 16 * STR_B; i += NTHR) bufB[i] = __float2half(0.f);
    if (tid < 64) {
        int r = tid >> 2, k = tid & 3;
        bufA[r * STR_A + 128 + k] = __float2half(x[(size_t)(b0 + r) * 256 + k]);
    }
    float c0r[4] = {0.f, 0.f, 0.f, 0.f};
    float c1r[4] = {0.f, 0.f, 0.f, 0.f};
    __syncthreads();

    float* gL0 = gbuf;
    float* gL1 = gbuf + 16 * GST;

    // ---------------- LSTM encoder, layer-pipelined superphases ----------------
    // superphase s: GEMM-L0 for t=s (s<64) and GEMM-L1 for t=s-1 (s>0) together.
    for (int s = 0; s <= S; s++) {
        const int p = s & 1, np = p ^ 1;
        __half* A0  = bufA + p * 16 * STR_A;
        __half* A0n = bufA + np * 16 * STR_A;
        __half* Bp  = bufB + p * 16 * STR_B;
        __half* Bn  = bufB + np * 16 * STR_B;

        if (s < S)  hgemm<4, 9>(A0, STR_A, g_wf_l0, wid * 4, gL0, GST);
        if (s > 0)  hgemm<4, 16>(Bp, STR_B, g_wf_l1, wid * 4, gL1, GST);
        __syncthreads();

        if (s < S) {   // combine L0 -> h0(s) into bufA[np] and bufB[np][0:128]
#pragma unroll
            for (int it = 0; it < 4; it++) {
                int idx = tid + it * NTHR;
                int r = idx >> 7, j = idx & 127;
                const float* gr = gL0 + r * GST;
                float ii = gr[j]       + g_b0[j];
                float ff = gr[128 + j] + g_b0[128 + j];
                float gg = gr[256 + j] + g_b0[256 + j];
                float oo = gr[384 + j] + g_b0[384 + j];
                float cc = sigm(ff) * c0r[it] + sigm(ii) * tanhf(gg);
                c0r[it] = cc;
                __half hh = __float2half(sigm(oo) * tanhf(cc));
                A0n[r * STR_A + j] = hh;
                Bn[r * STR_B + j] = hh;
            }
        }
        if (s > 0) {   // combine L1 -> h1(s-1) into bufB[np][128:256]
#pragma unroll
            for (int it = 0; it < 4; it++) {
                int idx = tid + it * NTHR;
                int r = idx >> 7, j = idx & 127;
                const float* gr = gL1 + r * GST;
                float ii = gr[j]       + g_b1[j];
                float ff = gr[128 + j] + g_b1[128 + j];
                float gg = gr[256 + j] + g_b1[256 + j];
                float oo = gr[384 + j] + g_b1[384 + j];
                float cc = sigm(ff) * c1r[it] + sigm(ii) * tanhf(gg);
                c1r[it] = cc;
                Bn[r * STR_B + 128 + j] = __float2half(sigm(oo) * tanhf(cc));
            }
        }
        if (s < S - 1 && tid < 64) {   // prefetch x(s+1) into bufA[np]
            int r = tid >> 2, k = tid & 3;
            A0n[r * STR_A + 128 + k] = xs[r * 256 + (s + 1) * 4 + k];
        }
        __syncthreads();
    }
    // finals: h0(63) in bufA buffer 0; h1(63) in bufB buffer 1 cols 128-255
    __half* h0f = bufA;
    __half* h1f = bufB + 16 * STR_B + 128;

    // ---------------- bridge ----------------
    if (wid < 8) hgemm<2, 8>(h0f, STR_A, g_wf_br, wid * 2, gbuf, GST);
    else         hgemm<2, 8>(h1f, STR_B, g_wf_br, (wid - 8) * 2, gbuf + 128, GST);
    __syncthreads();
#pragma unroll
    for (int it = 0; it < 4; it++) {
        int idx = tid + it * NTHR;
        int r = idx >> 7, j = idx & 127;
        float bv = brb[j];
        d0b[r * STR_D + j] = __float2half(tanhf(gbuf[r * GST + j] + bv));
        d1b[r * STR_D + j] = __float2half(tanhf(gbuf[r * GST + 128 + j] + bv));
    }
    __syncthreads();

    float* giB = gbuf;
    float* ghB = gbuf + 16 * GSTG;

    // ---------------- autoregressive GRU decode, heads folded into GEMM phases ----------------
    for (int t = 0; t < PRED; t++) {
        const int pg = t & 1, npg = pg ^ 1;
        __half* d0p = d0b + pg * 16 * STR_D;
        __half* d0n = d0b + npg * 16 * STR_D;
        __half* d1p = d1b + pg * 16 * STR_D;
        __half* d1n = d1b + npg * 16 * STR_D;
        const __half* A1 = (t == 0) ? h1f : d1p;
        const int a1str = (t == 0) ? STR_B : STR_D;

        // phase A: GRU L0 GEMMs + fc1(t-1)
        hgemm<3, 8>(A1, a1str, g_wf_gi0, wid * 3, giB, GSTG);
        hgemm<3, 8>(d0p, STR_D, g_wf_gh0, wid * 3, ghB, GSTG);
        if (t > 0) {
#pragma unroll
            for (int half = 0; half < 2; half++) {
                int o = tid + half * NTHR;
                int r = o >> 6, c = o & 63;
                float acc = fc1b[c];
#pragma unroll 4
                for (int k = 0; k < 128; k += 2) {
                    float2 fv = __half22float2(*(const __half2*)(d1p + r * STR_D + k));
                    acc = fmaf(fv.x, g_wfc1[(k + 0) * 64 + c], acc);
                    acc = fmaf(fv.y, g_wfc1[(k + 1) * 64 + c], acc);
                }
                fcz[r * 64 + c] = fmaxf(acc, 0.f);
            }
        }
        __syncthreads();
        // combine L0 -> d0n
#pragma unroll
        for (int it = 0; it < 4; it++) {
            int idx = tid + it * NTHR;
            int r = idx >> 7, j = idx & 127;
            const float* gi = giB + r * GSTG;
            const float* gh = ghB + r * GSTG;
            float rr = sigm(gi[j] + g_bgi0[j] + gh[j] + g_bgh0[j]);
            float zz = sigm(gi[128 + j] + g_bgi0[128 + j] + gh[128 + j] + g_bgh0[128 + j]);
            float nn = tanhf(gi[256 + j] + g_bgi0[256 + j] + rr * (gh[256 + j] + g_bgh0[256 + j]));
            float hold = __half2float(d0p[r * STR_D + j]);
            d0n[r * STR_D + j] = __float2half((1.f - zz) * nn + zz * hold);
        }
        __syncthreads();

        // phase B: GRU L1 GEMMs + fc2(t-1)
        hgemm<3, 8>(d0n, STR_D, g_wf_gi1, wid * 3, giB, GSTG);
        hgemm<3, 8>(d1p, STR_D, g_wf_gh1, wid * 3, ghB, GSTG);
        if (t > 0 && tid < 32) {
            int r = tid >> 1, cc = tid & 1;
            float s2 = fc2b[cc];
#pragma unroll
            for (int k = 0; k < 64; k++)
                s2 = fmaf(fcz[r * 64 + k], fc2w[cc * 64 + k], s2);
            out[(size_t)(b0 + r) * PRED * 2 + (t - 1) * 2 + cc] = s2;
        }
        __syncthreads();
        // combine L1 -> d1n
#pragma unroll
        for (int it = 0; it < 4; it++) {
            int idx = tid + it * NTHR;
            int r = idx >> 7, j = idx & 127;
            const float* gi = giB + r * GSTG;
            const float* gh = ghB + r * GSTG;
            float rr = sigm(gi[j] + g_bgi1[j] + gh[j] + g_bgh1[j]);
            float zz = sigm(gi[128 + j] + g_bgi1[128 + j] + gh[128 + j] + g_bgh1[128 + j]);
            float nn = tanhf(gi[256 + j] + g_bgi1[256 + j] + rr * (gh[256 + j] + g_bgh1[256 + j]));
            float hold = __half2float(d1p[r * STR_D + j]);
            d1n[r * STR_D + j] = __float2half((1.f - zz) * nn + zz * hold);
        }
        __syncthreads();
    }

    // ---------------- tail: head for t = PRED-1 (final d1 in buffer 0) ----------------
    {
        const __half* d1last = d1b;
#pragma unroll
        for (int half = 0; half < 2; half++) {
            int o = tid + half * NTHR;
            int r = o >> 6, c = o & 63;
            float acc = fc1b[c];
#pragma unroll 4
            for (int k = 0; k < 128; k += 2) {
                float2 fv = __half22float2(*(const __half2*)(d1last + r * STR_D + k));
                acc = fmaf(fv.x, g_wfc1[(k + 0) * 64 + c], acc);
                acc = fmaf(fv.y, g_wfc1[(k + 1) * 64 + c], acc);
            }
            fcz[r * 64 + c] = fmaxf(acc, 0.f);
        }
        __syncthreads();
        if (tid < 32) {
            int r = tid >> 1, cc = tid & 1;
            float s2 = fc2b[cc];
#pragma unroll
            for (int k = 0; k < 64; k++)
                s2 = fmaf(fcz[r * 64 + k], fc2w[cc * 64 + k], s2);
            out[(size_t)(b0 + r) * PRED * 2 + (PRED - 1) * 2 + cc] = s2;
        }
    }
}

extern "C" void kernel_launch(void* const* d_in, const int* in_sizes, int n_in,
                              void* d_out, int out_size)
{
    const float* p[24];
    int np = 0;
    for (int i = 0; i < n_in && np < 24; i++) {
        if (in_sizes[i] == 1) continue;
        p[np++] = (const float*)d_in[i];
    }
    const float* x = p[0];
    const float *lwih0 = p[1], *lwhh0 = p[2], *lbih0 = p[3], *lbhh0 = p[4];
    const float *lwih1 = p[5], *lwhh1 = p[6], *lbih1 = p[7], *lbhh1 = p[8];
    const float *gwi0 = p[9], *gwh0 = p[10], *gbi0 = p[11], *gbh0 = p[12];
    const float *gwi1 = p[13], *gwh1 = p[14], *gbi1 = p[15], *gbh1 = p[16];
    const float *brw = p[17], *brb = p[18];
    const float *fc1w = p[19], *fc1b = p[20];
    const float *fc2w = p[21], *fc2b = p[22];

    prep_kernel<<<512, 256>>>(lwih0, lwhh0, lbih0, lbhh0, lwih1, lwhh1, lbih1, lbhh1,
                              gwi0, gwh0, gbi0, gbh0, gwi1, gwh1, gbi1, gbh1,
                              brw, fc1w);

    const int smem = 122880;
    cudaFuncSetAttribute(rnn_kernel, cudaFuncAttributeMaxDynamicSharedMemorySize, smem);
    rnn_kernel<<<NBLK, NTHR, smem>>>(x, brb, fc1b, fc2w, fc2b, (float*)d_out);
}

// round 11
// speedup vs baseline: 1.5196x; 1.1141x over previous
#include <cuda_runtime.h>
#include <cuda_fp16.h>
#include <math.h>

#define H 128
#define S 64
#define PRED 50
#define BT 16
#define NBLK 128
#define NTHR 512

// ---------------- fragment-ordered weights: [ntile][kstep][lane][4 halves] ----------------
__device__ __align__(16) __half g_wf_l0[64 * 9 * 128];    // LSTM L0: K=144 (128 h + 4 x + pad)
__device__ __align__(16) __half g_wf_l1[64 * 16 * 128];   // LSTM L1: K=256 (wih1|whh1)
__device__ __align__(16) __half g_wf_gi0[48 * 8 * 128];   // GRU: K=128
__device__ __align__(16) __half g_wf_gh0[48 * 8 * 128];
__device__ __align__(16) __half g_wf_gi1[48 * 8 * 128];
__device__ __align__(16) __half g_wf_gh1[48 * 8 * 128];
__device__ __align__(16) __half g_wf_br[16 * 8 * 128];    // bridge
__device__ __align__(16) float  g_b0[512];
__device__ __align__(16) float  g_b1[512];
__device__ __align__(16) float  g_bgi0[384];
__device__ __align__(16) float  g_bgh0[384];
__device__ __align__(16) float  g_bgi1[384];
__device__ __align__(16) float  g_bgh1[384];
__device__ __align__(16) float  g_wfc1[128 * 64];         // [k][c] fp32

__global__ void prep_kernel(
    const float* __restrict__ lwih0, const float* __restrict__ lwhh0,
    const float* __restrict__ lbih0, const float* __restrict__ lbhh0,
    const float* __restrict__ lwih1, const float* __restrict__ lwhh1,
    const float* __restrict__ lbih1, const float* __restrict__ lbhh1,
    const float* __restrict__ gwi0, const float* __restrict__ gwh0,
    const float* __restrict__ gbi0, const float* __restrict__ gbh0,
    const float* __restrict__ gwi1, const float* __restrict__ gwh1,
    const float* __restrict__ gbi1, const float* __restrict__ gbh1,
    const float* __restrict__ brw, const float* __restrict__ fc1w)
{
    int i0 = blockIdx.x * blockDim.x + threadIdx.x;
    int st = gridDim.x * blockDim.x;

#define FRAG_DECODE(i, KS)                                  \
    int e = (i) & 3;                                        \
    int lane = ((i) >> 2) & 31;                             \
    int q2 = (i) >> 7;                                      \
    int s = q2 % (KS);                                      \
    int nt = q2 / (KS);                                     \
    int n = nt * 8 + (lane >> 2);                           \
    int k = s * 16 + (lane & 3) * 2 + (e & 1) + (e >> 1) * 8;

    for (int i = i0; i < 64 * 9 * 128; i += st) {
        FRAG_DECODE(i, 9);
        float v = 0.f;
        if (k < 128)      v = lwhh0[n * 128 + k];
        else if (k < 132) v = lwih0[n * 4 + (k - 128)];
        g_wf_l0[i] = __float2half(v);
    }
    for (int i = i0; i < 64 * 16 * 128; i += st) {
        FRAG_DECODE(i, 16);
        float v = (k < 128) ? lwih1[n * 128 + k] : lwhh1[n * 128 + (k - 128)];
        g_wf_l1[i] = __float2half(v);
    }
    for (int i = i0; i < 48 * 8 * 128; i += st) {
        FRAG_DECODE(i, 8);
        g_wf_gi0[i] = __float2half(gwi0[n * 128 + k]);
        g_wf_gh0[i] = __float2half(gwh0[n * 128 + k]);
        g_wf_gi1[i] = __float2half(gwi1[n * 128 + k]);
        g_wf_gh1[i] = __float2half(gwh1[n * 128 + k]);
    }
    for (int i = i0; i < 16 * 8 * 128; i += st) {
        FRAG_DECODE(i, 8);
        g_wf_br[i] = __float2half(brw[n * 128 + k]);
    }
#undef FRAG_DECODE
    for (int i = i0; i < 512; i += st) {
        g_b0[i] = lbih0[i] + lbhh0[i];
        g_b1[i] = lbih1[i] + lbhh1[i];
    }
    for (int i = i0; i < 384; i += st) {
        g_bgi0[i] = gbi0[i]; g_bgh0[i] = gbh0[i];
        g_bgi1[i] = gbi1[i]; g_bgh1[i] = gbh1[i];
    }
    for (int i = i0; i < 128 * 64; i += st) {
        int k = i / 64, c = i % 64;
        g_wfc1[i] = fc1w[c * 128 + k];
    }
}

// guaranteed-MUFU activations (independent of compiler math flags)
__device__ __forceinline__ float fast_tanh(float x) {
    float y;
    asm("tanh.approx.f32 %0, %1;" : "=f"(y) : "f"(x));
    return y;
}
__device__ __forceinline__ float fast_ex2(float x) {
    float y;
    asm("ex2.approx.f32 %0, %1;" : "=f"(y) : "f"(x));
    return y;
}
__device__ __forceinline__ float fast_rcp(float x) {
    float y;
    asm("rcp.approx.f32 %0, %1;" : "=f"(y) : "f"(x));
    return y;
}
__device__ __forceinline__ float sigm(float v) {
    return fast_rcp(1.f + fast_ex2(v * -1.44269504f));
}

__device__ __forceinline__ unsigned smem_u32(const void* p) {
    return (unsigned)__cvta_generic_to_shared(p);
}
__device__ __forceinline__ void ldsm_x4(unsigned addr, unsigned& r0, unsigned& r1,
                                        unsigned& r2, unsigned& r3) {
    asm volatile("ldmatrix.sync.aligned.m8n8.x4.shared.b16 {%0,%1,%2,%3}, [%4];\n"
                 : "=r"(r0), "=r"(r1), "=r"(r2), "=r"(r3) : "r"(addr));
}
__device__ __forceinline__ void hmma(float* c, unsigned a0, unsigned a1, unsigned a2,
                                     unsigned a3, unsigned b0, unsigned b1) {
    asm volatile("mma.sync.aligned.m16n8k16.row.col.f32.f16.f16.f32 "
                 "{%0,%1,%2,%3}, {%4,%5,%6,%7}, {%8,%9}, {%0,%1,%2,%3};\n"
                 : "+f"(c[0]), "+f"(c[1]), "+f"(c[2]), "+f"(c[3])
                 : "r"(a0), "r"(a1), "r"(a2), "r"(a3), "r"(b0), "r"(b1));
}

// Warp GEMM: C[16 x NT*8] = A[16 x KS*16] @ W, C -> smem fp32 (R7-proven mapping).
template<int NT, int KS>
__device__ __forceinline__ void hgemm(const __half* A, int astr,
                                      const __half* __restrict__ WF,
                                      int ntile0, float* outp, int ostr)
{
    const int lane = threadIdx.x & 31;
    unsigned abase = smem_u32(A) + (unsigned)(((lane & 15) * astr + ((lane >> 4) << 3)) * 2);
    float c[NT][4];
#pragma unroll
    for (int i = 0; i < NT; i++) { c[i][0] = c[i][1] = c[i][2] = c[i][3] = 0.f; }
#pragma unroll
    for (int s = 0; s < KS; s++) {
        unsigned a0, a1, a2, a3;
        ldsm_x4(abase + s * 32, a0, a1, a2, a3);
#pragma unroll
        for (int i = 0; i < NT; i++) {
            uint2 b = *(const uint2*)(WF + (((size_t)(ntile0 + i) * KS + s) * 32 + lane) * 4);
            hmma(c[i], a0, a1, a2, a3, b.x, b.y);
        }
    }
    const int gid = lane >> 2, tig = lane & 3;
#pragma unroll
    for (int i = 0; i < NT; i++) {
        int n = (ntile0 + i) * 8 + tig * 2;
        *(float2*)(outp + gid * ostr + n) = make_float2(c[i][0], c[i][1]);
        *(float2*)(outp + (gid + 8) * ostr + n) = make_float2(c[i][2], c[i][3]);
    }
}

#define STR_A  152
#define STR_B  264
#define STR_D  136
#define GST    520
#define GSTG   392

__global__ void __launch_bounds__(NTHR, 1) rnn_kernel(
    const float* __restrict__ x,
    const float* __restrict__ brb, const float* __restrict__ fc1b,
    const float* __restrict__ fc2w, const float* __restrict__ fc2b,
    float* __restrict__ out)
{
    extern __shared__ char smraw[];
    __half* xs   = (__half*)smraw;                 //  8192 B
    __half* bufA = (__half*)(smraw + 8192);        // [2][16][152]   9728 B
    __half* bufB = (__half*)(smraw + 17920);       // [2][16][264]  16896 B
    __half* d0b  = (__half*)(smraw + 34816);       // [2][16][136]   8704 B
    __half* d1b  = (__half*)(smraw + 43520);       // [2][16][136]   8704 B
    float*  gbuf = (float*)(smraw + 52224);        // 12544 floats  50176 B
    float*  fcz  = (float*)(smraw + 102400);       // [16][64]       4096 B

    const int tid = threadIdx.x;
    const int wid = tid >> 5;
    const int b0 = blockIdx.x * BT;

    // init: x tile, zero buffers, x_0 into bufA[0]
    for (int i = tid; i < BT * 256; i += NTHR) {
        int r = i >> 8, q = i & 255;
        xs[i] = __float2half(x[(size_t)(b0 + r) * 256 + q]);
    }
    for (int i = tid; i < 2 * 16 * STR_A; i += NTHR) bufA[i] = __float2half(0.f);
    for (int i = tid; i < 2 * 16 * STR_B; i += NTHR) bufB[i] = __float2half(0.f);
    if (tid < 64) {
        int r = tid >> 2, k = tid & 3;
        bufA[r * STR_A + 128 + k] = __float2half(x[(size_t)(b0 + r) * 256 + k]);
    }
    float c0r[4] = {0.f, 0.f, 0.f, 0.f};
    float c1r[4] = {0.f, 0.f, 0.f, 0.f};
    __syncthreads();

    // ---------------- LSTM encoder: exactly R7 (2 phases/step, one GEMM live per phase) ----------------
    for (int t = 0; t < S; t++) {
        const int p = t & 1, np = p ^ 1;
        __half* A0  = bufA + p * 16 * STR_A;
        __half* A0n = bufA + np * 16 * STR_A;
        __half* Bp  = bufB + p * 16 * STR_B;
        __half* Bn  = bufB + np * 16 * STR_B;

        // phase 1: L0 GEMM
        hgemm<4, 9>(A0, STR_A, g_wf_l0, wid * 4, gbuf, GST);
        __syncthreads();

        // combine L0 -> h0_new into bufA[np] and bufB[p][0:128]
#pragma unroll
        for (int it = 0; it < 4; it++) {
            int idx = tid + it * NTHR;
            int r = idx >> 7, j = idx & 127;
            const float* gr = gbuf + r * GST;
            float ii = gr[j]       + g_b0[j];
            float ff = gr[128 + j] + g_b0[128 + j];
            float gg = gr[256 + j] + g_b0[256 + j];
            float oo = gr[384 + j] + g_b0[384 + j];
            float cc = sigm(ff) * c0r[it] + sigm(ii) * fast_tanh(gg);
            c0r[it] = cc;
            __half hh = __float2half(sigm(oo) * fast_tanh(cc));
            A0n[r * STR_A + j] = hh;
            Bp[r * STR_B + j] = hh;
        }
        if (t < S - 1 && tid < 64) {
            int r = tid >> 2, k = tid & 3;
            A0n[r * STR_A + 128 + k] = xs[r * 256 + (t + 1) * 4 + k];
        }
        __syncthreads();

        // phase 2: L1 GEMM (concat-K) + combine
        hgemm<4, 16>(Bp, STR_B, g_wf_l1, wid * 4, gbuf, GST);
        __syncthreads();
#pragma unroll
        for (int it = 0; it < 4; it++) {
            int idx = tid + it * NTHR;
            int r = idx >> 7, j = idx & 127;
            const float* gr = gbuf + r * GST;
            float ii = gr[j]       + g_b1[j];
            float ff = gr[128 + j] + g_b1[128 + j];
            float gg = gr[256 + j] + g_b1[256 + j];
            float oo = gr[384 + j] + g_b1[384 + j];
            float cc = sigm(ff) * c1r[it] + sigm(ii) * fast_tanh(gg);
            c1r[it] = cc;
            Bn[r * STR_B + 128 + j] = __float2half(sigm(oo) * fast_tanh(cc));
        }
        __syncthreads();
    }
    __half* h0f = bufA;           // final h0 (buffer 0)
    __half* h1f = bufB + 128;     // final h1 (buffer 0, cols 128-255)

    // ---------------- bridge ----------------
    if (wid < 8) hgemm<2, 8>(h0f, STR_A, g_wf_br, wid * 2, gbuf, GST);
    else         hgemm<2, 8>(h1f, STR_B, g_wf_br, (wid - 8) * 2, gbuf + 128, GST);
    __syncthreads();
#pragma unroll
    for (int it = 0; it < 4; it++) {
        int idx = tid + it * NTHR;
        int r = idx >> 7, j = idx & 127;
        float bv = brb[j];
        d0b[r * STR_D + j] = __float2half(fast_tanh(gbuf[r * GST + j] + bv));
        d1b[r * STR_D + j] = __float2half(fast_tanh(gbuf[r * GST + 128 + j] + bv));
    }
    __syncthreads();

    float* giB = gbuf;                 // [16][392]
    float* ghB = gbuf + 16 * GSTG;     // [16][392]

    // ---------------- autoregressive GRU decode, heads folded into GEMM phases (4 syncs/step) ----------------
    for (int t = 0; t < PRED; t++) {
        const int pg = t & 1, npg = pg ^ 1;
        __half* d0p = d0b + pg * 16 * STR_D;
        __half* d0n = d0b + npg * 16 * STR_D;
        __half* d1p = d1b + pg * 16 * STR_D;
        __half* d1n = d1b + npg * 16 * STR_D;
        const __half* A1 = (t == 0) ? h1f : d1p;
        const int a1str = (t == 0) ? STR_B : STR_D;

        // phase A: GRU L0 GEMMs + fc1(t-1) [reads d1p, which this phase only reads]
        hgemm<3, 8>(A1, a1str, g_wf_gi0, wid * 3, giB, GSTG);
        hgemm<3, 8>(d0p, STR_D, g_wf_gh0, wid * 3, ghB, GSTG);
        if (t > 0) {
#pragma unroll
            for (int half = 0; half < 2; half++) {
                int o = tid + half * NTHR;
                int r = o >> 6, c = o & 63;
                float acc = fc1b[c];
#pragma unroll 4
                for (int k = 0; k < 128; k += 2) {
                    float2 fv = __half22float2(*(const __half2*)(d1p + r * STR_D + k));
                    acc = fmaf(fv.x, g_wfc1[(k + 0) * 64 + c], acc);
                    acc = fmaf(fv.y, g_wfc1[(k + 1) * 64 + c], acc);
                }
                fcz[r * 64 + c] = fmaxf(acc, 0.f);
            }
        }
        __syncthreads();

        // combine L0 -> d0n
#pragma unroll
        for (int it = 0; it < 4; it++) {
            int idx = tid + it * NTHR;
            int r = idx >> 7, j = idx & 127;
            const float* gi = giB + r * GSTG;
            const float* gh = ghB + r * GSTG;
            float rr = sigm(gi[j] + g_bgi0[j] + gh[j] + g_bgh0[j]);
            float zz = sigm(gi[128 + j] + g_bgi0[128 + j] + gh[128 + j] + g_bgh0[128 + j]);
            float nn = fast_tanh(gi[256 + j] + g_bgi0[256 + j] + rr * (gh[256 + j] + g_bgh0[256 + j]));
            float hold = __half2float(d0p[r * STR_D + j]);
            d0n[r * STR_D + j] = __float2half((1.f - zz) * nn + zz * hold);
        }
        __syncthreads();

        // phase B: GRU L1 GEMMs + fc2(t-1)
        hgemm<3, 8>(d0n, STR_D, g_wf_gi1, wid * 3, giB, GSTG);
        hgemm<3, 8>(d1p, STR_D, g_wf_gh1, wid * 3, ghB, GSTG);
        if (t > 0 && tid < 32) {
            int r = tid >> 1, cc = tid & 1;
            float s2 = fc2b[cc];
#pragma unroll
            for (int k = 0; k < 64; k++)
                s2 = fmaf(fcz[r * 64 + k], fc2w[cc * 64 + k], s2);
            out[(size_t)(b0 + r) * PRED * 2 + (t - 1) * 2 + cc] = s2;
        }
        __syncthreads();

        // combine L1 -> d1n
#pragma unroll
        for (int it = 0; it < 4; it++) {
            int idx = tid + it * NTHR;
            int r = idx >> 7, j = idx & 127;
            const float* gi = giB + r * GSTG;
            const float* gh = ghB + r * GSTG;
            float rr = sigm(gi[j] + g_bgi1[j] + gh[j] + g_bgh1[j]);
            float zz = sigm(gi[128 + j] + g_bgi1[128 + j] + gh[128 + j] + g_bgh1[128 + j]);
            float nn = fast_tanh(gi[256 + j] + g_bgi1[256 + j] + rr * (gh[256 + j] + g_bgh1[256 + j]));
            float hold = __half2float(d1p[r * STR_D + j]);
            d1n[r * STR_D + j] = __float2half((1.f - zz) * nn + zz * hold);
        }
        __syncthreads();
    }

    // ---------------- tail: head for t = PRED-1 (final d1 in buffer 0) ----------------
    {
        const __half* d1last = d1b;
#pragma unroll
        for (int half = 0; half < 2; half++) {
            int o = tid + half * NTHR;
            int r = o >> 6, c = o & 63;
            float acc = fc1b[c];
#pragma unroll 4
            for (int k = 0; k < 128; k += 2) {
                float2 fv = __half22float2(*(const __half2*)(d1last + r * STR_D + k));
                acc = fmaf(fv.x, g_wfc1[(k + 0) * 64 + c], acc);
                acc = fmaf(fv.y, g_wfc1[(k + 1) * 64 + c], acc);
            }
            fcz[r * 64 + c] = fmaxf(acc, 0.f);
        }
        __syncthreads();
        if (tid < 32) {
            int r = tid >> 1, cc = tid & 1;
            float s2 = fc2b[cc];
#pragma unroll
            for (int k = 0; k < 64; k++)
                s2 = fmaf(fcz[r * 64 + k], fc2w[cc * 64 + k], s2);
            out[(size_t)(b0 + r) * PRED * 2 + (PRED - 1) * 2 + cc] = s2;
        }
    }
}

extern "C" void kernel_launch(void* const* d_in, const int* in_sizes, int n_in,
                              void* d_out, int out_size)
{
    const float* p[24];
    int np = 0;
    for (int i = 0; i < n_in && np < 24; i++) {
        if (in_sizes[i] == 1) continue;
        p[np++] = (const float*)d_in[i];
    }
    const float* x = p[0];
    const float *lwih0 = p[1], *lwhh0 = p[2], *lbih0 = p[3], *lbhh0 = p[4];
    const float *lwih1 = p[5], *lwhh1 = p[6], *lbih1 = p[7], *lbhh1 = p[8];
    const float *gwi0 = p[9], *gwh0 = p[10], *gbi0 = p[11], *gbh0 = p[12];
    const float *gwi1 = p[13], *gwh1 = p[14], *gbi1 = p[15], *gbh1 = p[16];
    const float *brw = p[17], *brb = p[18];
    const float *fc1w = p[19], *fc1b = p[20];
    const float *fc2w = p[21], *fc2b = p[22];

    prep_kernel<<<512, 256>>>(lwih0, lwhh0, lbih0, lbhh0, lwih1, lwhh1, lbih1, lbhh1,
                              gwi0, gwh0, gbi0, gbh0, gwi1, gwh1, gbi1, gbh1,
                              brw, fc1w);

    const int smem = 106496;
    cudaFuncSetAttribute(rnn_kernel, cudaFuncAttributeMaxDynamicSharedMemorySize, smem);
    rnn_kernel<<<NBLK, NTHR, smem>>>(x, brb, fc1b, fc2w, fc2b, (float*)d_out);
}

// round 12
// speedup vs baseline: 1.8763x; 1.2347x over previous
#include <cuda_runtime.h>
#include <cuda_fp16.h>
#include <math.h>

#define H 128
#define S 64
#define PRED 50
#define BT 16
#define NBLK 128
#define NTHR 512

// ---------------- fragment-ordered weights ----------------
// LSTM/bridge: natural column order (R7). GRU: GATE-INTERLEAVED — warp w's 3 tiles
// are gates r,z,n of units [w*8, w*8+8), so the combine happens in registers.
__device__ __align__(16) __half g_wf_l0[64 * 9 * 128];    // LSTM L0: K=144 (128 h + 4 x + pad)
__device__ __align__(16) __half g_wf_l1[64 * 16 * 128];   // LSTM L1: K=256 (wih1|whh1)
__device__ __align__(16) __half g_wf_gi0[48 * 8 * 128];   // GRU, gate-interleaved
__device__ __align__(16) __half g_wf_gh0[48 * 8 * 128];
__device__ __align__(16) __half g_wf_gi1[48 * 8 * 128];
__device__ __align__(16) __half g_wf_gh1[48 * 8 * 128];
__device__ __align__(16) __half g_wf_br[16 * 8 * 128];    // bridge (natural)
__device__ __align__(16) float  g_b0[512];
__device__ __align__(16) float  g_b1[512];
__device__ __align__(16) float  g_gb[1024];   // per GRU layer: [0:256) r,z bias sums; [256:384) bin; [384:512) bhn
__device__ __align__(16) float  g_wfc1[128 * 64];         // [k][c] fp32

__global__ void prep_kernel(
    const float* __restrict__ lwih0, const float* __restrict__ lwhh0,
    const float* __restrict__ lbih0, const float* __restrict__ lbhh0,
    const float* __restrict__ lwih1, const float* __restrict__ lwhh1,
    const float* __restrict__ lbih1, const float* __restrict__ lbhh1,
    const float* __restrict__ gwi0, const float* __restrict__ gwh0,
    const float* __restrict__ gbi0, const float* __restrict__ gbh0,
    const float* __restrict__ gwi1, const float* __restrict__ gwh1,
    const float* __restrict__ gbi1, const float* __restrict__ gbh1,
    const float* __restrict__ brw, const float* __restrict__ fc1w)
{
    int i0 = blockIdx.x * blockDim.x + threadIdx.x;
    int st = gridDim.x * blockDim.x;

#define FRAG_DECODE(i, KS)                                  \
    int e = (i) & 3;                                        \
    int lane = ((i) >> 2) & 31;                             \
    int q2 = (i) >> 7;                                      \
    int s = q2 % (KS);                                      \
    int nt = q2 / (KS);                                     \
    int gid = lane >> 2;                                    \
    int k = s * 16 + (lane & 3) * 2 + (e & 1) + (e >> 1) * 8;

    for (int i = i0; i < 64 * 9 * 128; i += st) {
        FRAG_DECODE(i, 9);
        int n = nt * 8 + gid;                       // natural
        float v = 0.f;
        if (k < 128)      v = lwhh0[n * 128 + k];
        else if (k < 132) v = lwih0[n * 4 + (k - 128)];
        g_wf_l0[i] = __float2half(v);
    }
    for (int i = i0; i < 64 * 16 * 128; i += st) {
        FRAG_DECODE(i, 16);
        int n = nt * 8 + gid;                       // natural
        float v = (k < 128) ? lwih1[n * 128 + k] : lwhh1[n * 128 + (k - 128)];
        g_wf_l1[i] = __float2half(v);
    }
    for (int i = i0; i < 48 * 8 * 128; i += st) {
        FRAG_DECODE(i, 8);
        int n = (nt % 3) * 128 + (nt / 3) * 8 + gid;  // gate-interleaved
        g_wf_gi0[i] = __float2half(gwi0[n * 128 + k]);
        g_wf_gh0[i] = __float2half(gwh0[n * 128 + k]);
        g_wf_gi1[i] = __float2half(gwi1[n * 128 + k]);
        g_wf_gh1[i] = __float2half(gwh1[n * 128 + k]);
    }
    for (int i = i0; i < 16 * 8 * 128; i += st) {
        FRAG_DECODE(i, 8);
        int n = nt * 8 + gid;                       // natural
        g_wf_br[i] = __float2half(brw[n * 128 + k]);
    }
#undef FRAG_DECODE
    for (int i = i0; i < 512; i += st) {
        g_b0[i] = lbih0[i] + lbhh0[i];
        g_b1[i] = lbih1[i] + lbhh1[i];
    }
    for (int i = i0; i < 1024; i += st) {
        int l = i >> 9, q = i & 511;
        int reg = q >> 7, j = q & 127;
        const float* bi = l ? gbi1 : gbi0;
        const float* bh = l ? gbh1 : gbh0;
        float v;
        if (reg == 0)      v = bi[j] + bh[j];               // r-gate combined
        else if (reg == 1) v = bi[128 + j] + bh[128 + j];   // z-gate combined
        else if (reg == 2) v = bi[256 + j];                  // n input bias
        else               v = bh[256 + j];                  // n hidden bias
        g_gb[i] = v;
    }
    for (int i = i0; i < 128 * 64; i += st) {
        int k = i / 64, c = i % 64;
        g_wfc1[i] = fc1w[c * 128 + k];
    }
}

// guaranteed-MUFU activations
__device__ __forceinline__ float fast_tanh(float x) {
    float y; asm("tanh.approx.f32 %0, %1;" : "=f"(y) : "f"(x)); return y;
}
__device__ __forceinline__ float fast_ex2(float x) {
    float y; asm("ex2.approx.f32 %0, %1;" : "=f"(y) : "f"(x)); return y;
}
__device__ __forceinline__ float fast_rcp(float x) {
    float y; asm("rcp.approx.f32 %0, %1;" : "=f"(y) : "f"(x)); return y;
}
__device__ __forceinline__ float sigm(float v) {
    return fast_rcp(1.f + fast_ex2(v * -1.44269504f));
}

__device__ __forceinline__ unsigned smem_u32(const void* p) {
    return (unsigned)__cvta_generic_to_shared(p);
}
__device__ __forceinline__ void ldsm_x4(unsigned addr, unsigned& r0, unsigned& r1,
                                        unsigned& r2, unsigned& r3) {
    asm volatile("ldmatrix.sync.aligned.m8n8.x4.shared.b16 {%0,%1,%2,%3}, [%4];\n"
                 : "=r"(r0), "=r"(r1), "=r"(r2), "=r"(r3) : "r"(addr));
}
__device__ __forceinline__ void hmma(float* c, unsigned a0, unsigned a1, unsigned a2,
                                     unsigned a3, unsigned b0, unsigned b1) {
    asm volatile("mma.sync.aligned.m16n8k16.row.col.f32.f16.f16.f32 "
                 "{%0,%1,%2,%3}, {%4,%5,%6,%7}, {%8,%9}, {%0,%1,%2,%3};\n"
                 : "+f"(c[0]), "+f"(c[1]), "+f"(c[2]), "+f"(c[3])
                 : "r"(a0), "r"(a1), "r"(a2), "r"(a3), "r"(b0), "r"(b1));
}

// register-accumulator warp GEMM
template<int NT, int KS>
__device__ __forceinline__ void hgemm_reg(const __half* A, int astr,
                                          const __half* __restrict__ WF,
                                          int ntile0, float (&c)[NT][4])
{
    const int lane = threadIdx.x & 31;
    unsigned abase = smem_u32(A) + (unsigned)(((lane & 15) * astr + ((lane >> 4) << 3)) * 2);
#pragma unroll
    for (int i = 0; i < NT; i++) { c[i][0] = c[i][1] = c[i][2] = c[i][3] = 0.f; }
#pragma unroll
    for (int s = 0; s < KS; s++) {
        unsigned a0, a1, a2, a3;
        ldsm_x4(abase + s * 32, a0, a1, a2, a3);
#pragma unroll
        for (int i = 0; i < NT; i++) {
            uint2 b = *(const uint2*)(WF + (((size_t)(ntile0 + i) * KS + s) * 32 + lane) * 4);
            hmma(c[i], a0, a1, a2, a3, b.x, b.y);
        }
    }
}

// smem-output variant (LSTM + bridge)
template<int NT, int KS>
__device__ __forceinline__ void hgemm(const __half* A, int astr,
                                      const __half* __restrict__ WF,
                                      int ntile0, float* outp, int ostr)
{
    float c[NT][4];
    hgemm_reg<NT, KS>(A, astr, WF, ntile0, c);
    const int lane = threadIdx.x & 31;
    const int gid = lane >> 2, tig = lane & 3;
#pragma unroll
    for (int i = 0; i < NT; i++) {
        int n = (ntile0 + i) * 8 + tig * 2;
        *(float2*)(outp + gid * ostr + n) = make_float2(c[i][0], c[i][1]);
        *(float2*)(outp + (gid + 8) * ostr + n) = make_float2(c[i][2], c[i][3]);
    }
}

#define STR_A  152
#define STR_B  264
#define STR_D  136
#define GST    520

__global__ void __launch_bounds__(NTHR, 1) rnn_kernel(
    const float* __restrict__ x,
    const float* __restrict__ brb, const float* __restrict__ fc1b,
    const float* __restrict__ fc2w, const float* __restrict__ fc2b,
    float* __restrict__ out)
{
    extern __shared__ char smraw[];
    __half* xs   = (__half*)smraw;                 //  8192 B
    __half* bufA = (__half*)(smraw + 8192);        // [2][16][152]   9728 B
    __half* bufB = (__half*)(smraw + 17920);       // [2][16][264]  16896 B
    __half* d0b  = (__half*)(smraw + 34816);       // [2][16][136]   8704 B
    __half* d1b  = (__half*)(smraw + 43520);       // [2][16][136]   8704 B
    float*  gbuf = (float*)(smraw + 52224);        // [16][520]     33280 B (LSTM/bridge)
    float*  fcz  = (float*)(smraw + 85504);        // [16][64]       4096 B
    float*  sgb  = (float*)(smraw + 89600);        // [2][512]       4096 B (GRU biases)

    const int tid = threadIdx.x;
    const int wid = tid >> 5;
    const int lane = tid & 31;
    const int gid = lane >> 2, tig = lane & 3;
    const int j0 = wid * 8 + tig * 2;              // GRU: this thread's 2 units
    const int b0 = blockIdx.x * BT;

    // init
    for (int i = tid; i < BT * 256; i += NTHR) {
        int r = i >> 8, q = i & 255;
        xs[i] = __float2half(x[(size_t)(b0 + r) * 256 + q]);
    }
    for (int i = tid; i < 2 * 16 * STR_A; i += NTHR) bufA[i] = __float2half(0.f);
    for (int i = tid; i < 2 * 16 * STR_B; i += NTHR) bufB[i] = __float2half(0.f);
    for (int i = tid; i < 1024; i += NTHR) sgb[i] = g_gb[i];
    if (tid < 64) {
        int r = tid >> 2, k = tid & 3;
        bufA[r * STR_A + 128 + k] = __float2half(x[(size_t)(b0 + r) * 256 + k]);
    }
    float c0r[4] = {0.f, 0.f, 0.f, 0.f};
    float c1r[4] = {0.f, 0.f, 0.f, 0.f};
    __syncthreads();

    // ---------------- LSTM encoder (exactly R7 structure) ----------------
    for (int t = 0; t < S; t++) {
        const int p = t & 1, np = p ^ 1;
        __half* A0  = bufA + p * 16 * STR_A;
        __half* A0n = bufA + np * 16 * STR_A;
        __half* Bp  = bufB + p * 16 * STR_B;
        __half* Bn  = bufB + np * 16 * STR_B;

        hgemm<4, 9>(A0, STR_A, g_wf_l0, wid * 4, gbuf, GST);
        __syncthreads();
#pragma unroll
        for (int it = 0; it < 4; it++) {
            int idx = tid + it * NTHR;
            int r = idx >> 7, j = idx & 127;
            const float* gr = gbuf + r * GST;
            float ii = gr[j]       + g_b0[j];
            float ff = gr[128 + j] + g_b0[128 + j];
            float gg = gr[256 + j] + g_b0[256 + j];
            float oo = gr[384 + j] + g_b0[384 + j];
            float cc = sigm(ff) * c0r[it] + sigm(ii) * fast_tanh(gg);
            c0r[it] = cc;
            __half hh = __float2half(sigm(oo) * fast_tanh(cc));
            A0n[r * STR_A + j] = hh;
            Bp[r * STR_B + j] = hh;
        }
        if (t < S - 1 && tid < 64) {
            int r = tid >> 2, k = tid & 3;
            A0n[r * STR_A + 128 + k] = xs[r * 256 + (t + 1) * 4 + k];
        }
        __syncthreads();

        hgemm<4, 16>(Bp, STR_B, g_wf_l1, wid * 4, gbuf, GST);
        __syncthreads();
#pragma unroll
        for (int it = 0; it < 4; it++) {
            int idx = tid + it * NTHR;
            int r = idx >> 7, j = idx & 127;
            const float* gr = gbuf + r * GST;
            float ii = gr[j]       + g_b1[j];
            float ff = gr[128 + j] + g_b1[128 + j];
            float gg = gr[256 + j] + g_b1[256 + j];
            float oo = gr[384 + j] + g_b1[384 + j];
            float cc = sigm(ff) * c1r[it] + sigm(ii) * fast_tanh(gg);
            c1r[it] = cc;
            Bn[r * STR_B + 128 + j] = __float2half(sigm(oo) * fast_tanh(cc));
        }
        __syncthreads();
    }
    __half* h0f = bufA;           // final h0 (buffer 0)
    __half* h1f = bufB + 128;     // final h1 (buffer 0, cols 128-255)

    // ---------------- bridge ----------------
    if (wid < 8) hgemm<2, 8>(h0f, STR_A, g_wf_br, wid * 2, gbuf, GST);
    else         hgemm<2, 8>(h1f, STR_B, g_wf_br, (wid - 8) * 2, gbuf + 128, GST);
    __syncthreads();
#pragma unroll
    for (int it = 0; it < 4; it++) {
        int idx = tid + it * NTHR;
        int r = idx >> 7, j = idx & 127;
        float bv = brb[j];
        d0b[r * STR_D + j] = __float2half(fast_tanh(gbuf[r * GST + j] + bv));
        d1b[r * STR_D + j] = __float2half(fast_tanh(gbuf[r * GST + 128 + j] + bv));
    }
    __syncthreads();

    const float* sgb0 = sgb;
    const float* sgb1 = sgb + 512;

    // ---------------- autoregressive GRU decode: in-register combine, 4 syncs/step ----------------
    for (int t = 0; t < PRED; t++) {
        const int pg = t & 1, npg = pg ^ 1;
        __half* d0p = d0b + pg * 16 * STR_D;
        __half* d0n = d0b + npg * 16 * STR_D;
        __half* d1p = d1b + pg * 16 * STR_D;
        __half* d1n = d1b + npg * 16 * STR_D;
        const __half* A1 = (t == 0) ? h1f : d1p;
        const int a1str = (t == 0) ? STR_B : STR_D;

        // phase A: GRU L0 GEMMs + in-register combine -> d0n
        {
            float ai[3][4], ah[3][4];
            hgemm_reg<3, 8>(A1, a1str, g_wf_gi0, wid * 3, ai);
            hgemm_reg<3, 8>(d0p, STR_D, g_wf_gh0, wid * 3, ah);
            float val[2][2];
#pragma unroll
            for (int rs = 0; rs < 2; rs++)
#pragma unroll
                for (int e = 0; e < 2; e++) {
                    int ix = rs * 2 + e;
                    float rr = sigm(ai[0][ix] + ah[0][ix] + sgb0[j0 + e]);
                    float zz = sigm(ai[1][ix] + ah[1][ix] + sgb0[128 + j0 + e]);
                    float nn = fast_tanh(ai[2][ix] + sgb0[256 + j0 + e]
                                         + rr * (ah[2][ix] + sgb0[384 + j0 + e]));
                    float hold = __half2float(d0p[(gid + rs * 8) * STR_D + j0 + e]);
                    val[rs][e] = (1.f - zz) * nn + zz * hold;
                }
            *(__half2*)(d0n + gid * STR_D + j0) = __floats2half2_rn(val[0][0], val[0][1]);
            *(__half2*)(d0n + (gid + 8) * STR_D + j0) = __floats2half2_rn(val[1][0], val[1][1]);
        }
        __syncthreads();

        // phase B: GRU L1 GEMMs + in-register combine -> d1n
        {
            float ai[3][4], ah[3][4];
            hgemm_reg<3, 8>(d0n, STR_D, g_wf_gi1, wid * 3, ai);
            hgemm_reg<3, 8>(d1p, STR_D, g_wf_gh1, wid * 3, ah);
            float val[2][2];
#pragma unroll
            for (int rs = 0; rs < 2; rs++)
#pragma unroll
                for (int e = 0; e < 2; e++) {
                    int ix = rs * 2 + e;
                    float rr = sigm(ai[0][ix] + ah[0][ix] + sgb1[j0 + e]);
                    float zz = sigm(ai[1][ix] + ah[1][ix] + sgb1[128 + j0 + e]);
                    float nn = fast_tanh(ai[2][ix] + sgb1[256 + j0 + e]
                                         + rr * (ah[2][ix] + sgb1[384 + j0 + e]));
                    float hold = __half2float(d1p[(gid + rs * 8) * STR_D + j0 + e]);
                    val[rs][e] = (1.f - zz) * nn + zz * hold;
                }
            *(__half2*)(d1n + gid * STR_D + j0) = __floats2half2_rn(val[0][0], val[0][1]);
            *(__half2*)(d1n + (gid + 8) * STR_D + j0) = __floats2half2_rn(val[1][0], val[1][1]);
        }
        __syncthreads();

        // phase C: fc1 (relu) on d1n
#pragma unroll
        for (int half = 0; half < 2; half++) {
            int o = tid + half * NTHR;
            int r = o >> 6, c = o & 63;
            float acc = fc1b[c];
#pragma unroll 4
            for (int k = 0; k < 128; k += 2) {
                float2 fv = __half22float2(*(const __half2*)(d1n + r * STR_D + k));
                acc = fmaf(fv.x, g_wfc1[(k + 0) * 64 + c], acc);
                acc = fmaf(fv.y, g_wfc1[(k + 1) * 64 + c], acc);
            }
            fcz[r * 64 + c] = fmaxf(acc, 0.f);
        }
        __syncthreads();

        // phase D: fc2
        if (tid < 32) {
            int r = tid >> 1, cc = tid & 1;
            float s2 = fc2b[cc];
#pragma unroll
            for (int k = 0; k < 64; k++)
                s2 = fmaf(fcz[r * 64 + k], fc2w[cc * 64 + k], s2);
            out[(size_t)(b0 + r) * PRED * 2 + t * 2 + cc] = s2;
        }
        __syncthreads();
    }
}

extern "C" void kernel_launch(void* const* d_in, const int* in_sizes, int n_in,
                              void* d_out, int out_size)
{
    const float* p[24];
    int np = 0;
    for (int i = 0; i < n_in && np < 24; i++) {
        if (in_sizes[i] == 1) continue;
        p[np++] = (const float*)d_in[i];
    }
    const float* x = p[0];
    const float *lwih0 = p[1], *lwhh0 = p[2], *lbih0 = p[3], *lbhh0 = p[4];
    const float *lwih1 = p[5], *lwhh1 = p[6], *lbih1 = p[7], *lbhh1 = p[8];
    const float *gwi0 = p[9], *gwh0 = p[10], *gbi0 = p[11], *gbh0 = p[12];
    const float *gwi1 = p[13], *gwh1 = p[14], *gbi1 = p[15], *gbh1 = p[16];
    const float *brw = p[17], *brb = p[18];
    const float *fc1w = p[19], *fc1b = p[20];
    const float *fc2w = p[21], *fc2b = p[22];

    prep_kernel<<<512, 256>>>(lwih0, lwhh0, lbih0, lbhh0, lwih1, lwhh1, lbih1, lbhh1,
                              gwi0, gwh0, gbi0, gbh0, gwi1, gwh1, gbi1, gbh1,
                              brw, fc1w);

    const int smem = 93696;
    cudaFuncSetAttribute(rnn_kernel, cudaFuncAttributeMaxDynamicSharedMemorySize, smem);
    rnn_kernel<<<NBLK, NTHR, smem>>>(x, brb, fc1b, fc2w, fc2b, (float*)d_out);
}

// round 13
// speedup vs baseline: 1.9594x; 1.0443x over previous
#include <cuda_runtime.h>
#include <cuda_fp16.h>
#include <math.h>

#define H 128
#define S 64
#define PRED 50
#define BT 16
#define NBLK 128
#define NTHR 512

// ---------------- fragment-ordered weights, GATE-INTERLEAVED everywhere ----------------
// Warp w's tiles hold all gates of units [w*8, w*8+8): LSTM nt=w*4+g, GRU nt=w*3+g.
__device__ __align__(16) __half g_wf_l0[64 * 9 * 128];    // LSTM L0: K=144 (128 h + 4 x + pad)
__device__ __align__(16) __half g_wf_l1[64 * 16 * 128];   // LSTM L1: K=256 (wih1|whh1)
__device__ __align__(16) __half g_wf_gi0[48 * 8 * 128];   // GRU, gate-interleaved
__device__ __align__(16) __half g_wf_gh0[48 * 8 * 128];
__device__ __align__(16) __half g_wf_gi1[48 * 8 * 128];
__device__ __align__(16) __half g_wf_gh1[48 * 8 * 128];
__device__ __align__(16) __half g_wf_br[16 * 8 * 128];    // bridge (natural)
__device__ __align__(16) float  g_b0[512];                // LSTM biases, natural n = g*128+j
__device__ __align__(16) float  g_b1[512];
__device__ __align__(16) float  g_gb[1024];   // GRU biases: per layer [0:128) r, [128:256) z, [256:384) bin, [384:512) bhn
__device__ __align__(16) float  g_wfc1[128 * 64];         // [k][c] fp32

__global__ void prep_kernel(
    const float* __restrict__ lwih0, const float* __restrict__ lwhh0,
    const float* __restrict__ lbih0, const float* __restrict__ lbhh0,
    const float* __restrict__ lwih1, const float* __restrict__ lwhh1,
    const float* __restrict__ lbih1, const float* __restrict__ lbhh1,
    const float* __restrict__ gwi0, const float* __restrict__ gwh0,
    const float* __restrict__ gbi0, const float* __restrict__ gbh0,
    const float* __restrict__ gwi1, const float* __restrict__ gwh1,
    const float* __restrict__ gbi1, const float* __restrict__ gbh1,
    const float* __restrict__ brw, const float* __restrict__ fc1w)
{
    int i0 = blockIdx.x * blockDim.x + threadIdx.x;
    int st = gridDim.x * blockDim.x;

#define FRAG_DECODE(i, KS)                                  \
    int e = (i) & 3;                                        \
    int lane = ((i) >> 2) & 31;                             \
    int q2 = (i) >> 7;                                      \
    int s = q2 % (KS);                                      \
    int nt = q2 / (KS);                                     \
    int gid = lane >> 2;                                    \
    int k = s * 16 + (lane & 3) * 2 + (e & 1) + (e >> 1) * 8;

    for (int i = i0; i < 64 * 9 * 128; i += st) {
        FRAG_DECODE(i, 9);
        int n = (nt & 3) * 128 + (nt >> 2) * 8 + gid;   // gate-interleaved
        float v = 0.f;
        if (k < 128)      v = lwhh0[n * 128 + k];
        else if (k < 132) v = lwih0[n * 4 + (k - 128)];
        g_wf_l0[i] = __float2half(v);
    }
    for (int i = i0; i < 64 * 16 * 128; i += st) {
        FRAG_DECODE(i, 16);
        int n = (nt & 3) * 128 + (nt >> 2) * 8 + gid;   // gate-interleaved
        float v = (k < 128) ? lwih1[n * 128 + k] : lwhh1[n * 128 + (k - 128)];
        g_wf_l1[i] = __float2half(v);
    }
    for (int i = i0; i < 48 * 8 * 128; i += st) {
        FRAG_DECODE(i, 8);
        int n = (nt % 3) * 128 + (nt / 3) * 8 + gid;    // gate-interleaved
        g_wf_gi0[i] = __float2half(gwi0[n * 128 + k]);
        g_wf_gh0[i] = __float2half(gwh0[n * 128 + k]);
        g_wf_gi1[i] = __float2half(gwi1[n * 128 + k]);
        g_wf_gh1[i] = __float2half(gwh1[n * 128 + k]);
    }
    for (int i = i0; i < 16 * 8 * 128; i += st) {
        FRAG_DECODE(i, 8);
        int n = nt * 8 + gid;                            // natural
        g_wf_br[i] = __float2half(brw[n * 128 + k]);
    }
#undef FRAG_DECODE
    for (int i = i0; i < 512; i += st) {
        g_b0[i] = lbih0[i] + lbhh0[i];
        g_b1[i] = lbih1[i] + lbhh1[i];
    }
    for (int i = i0; i < 1024; i += st) {
        int l = i >> 9, q = i & 511;
        int reg = q >> 7, j = q & 127;
        const float* bi = l ? gbi1 : gbi0;
        const float* bh = l ? gbh1 : gbh0;
        float v;
        if (reg == 0)      v = bi[j] + bh[j];
        else if (reg == 1) v = bi[128 + j] + bh[128 + j];
        else if (reg == 2) v = bi[256 + j];
        else               v = bh[256 + j];
        g_gb[i] = v;
    }
    for (int i = i0; i < 128 * 64; i += st) {
        int k = i / 64, c = i % 64;
        g_wfc1[i] = fc1w[c * 128 + k];
    }
}

// guaranteed-MUFU activations
__device__ __forceinline__ float fast_tanh(float x) {
    float y; asm("tanh.approx.f32 %0, %1;" : "=f"(y) : "f"(x)); return y;
}
__device__ __forceinline__ float fast_ex2(float x) {
    float y; asm("ex2.approx.f32 %0, %1;" : "=f"(y) : "f"(x)); return y;
}
__device__ __forceinline__ float fast_rcp(float x) {
    float y; asm("rcp.approx.f32 %0, %1;" : "=f"(y) : "f"(x)); return y;
}
__device__ __forceinline__ float sigm(float v) {
    return fast_rcp(1.f + fast_ex2(v * -1.44269504f));
}

__device__ __forceinline__ unsigned smem_u32(const void* p) {
    return (unsigned)__cvta_generic_to_shared(p);
}
__device__ __forceinline__ void ldsm_x4(unsigned addr, unsigned& r0, unsigned& r1,
                                        unsigned& r2, unsigned& r3) {
    asm volatile("ldmatrix.sync.aligned.m8n8.x4.shared.b16 {%0,%1,%2,%3}, [%4];\n"
                 : "=r"(r0), "=r"(r1), "=r"(r2), "=r"(r3) : "r"(addr));
}
__device__ __forceinline__ void hmma(float* c, unsigned a0, unsigned a1, unsigned a2,
                                     unsigned a3, unsigned b0, unsigned b1) {
    asm volatile("mma.sync.aligned.m16n8k16.row.col.f32.f16.f16.f32 "
                 "{%0,%1,%2,%3}, {%4,%5,%6,%7}, {%8,%9}, {%0,%1,%2,%3};\n"
                 : "+f"(c[0]), "+f"(c[1]), "+f"(c[2]), "+f"(c[3])
                 : "r"(a0), "r"(a1), "r"(a2), "r"(a3), "r"(b0), "r"(b1));
}

// register-accumulator warp GEMM
template<int NT, int KS>
__device__ __forceinline__ void hgemm_reg(const __half* A, int astr,
                                          const __half* __restrict__ WF,
                                          int ntile0, float (&c)[NT][4])
{
    const int lane = threadIdx.x & 31;
    unsigned abase = smem_u32(A) + (unsigned)(((lane & 15) * astr + ((lane >> 4) << 3)) * 2);
#pragma unroll
    for (int i = 0; i < NT; i++) { c[i][0] = c[i][1] = c[i][2] = c[i][3] = 0.f; }
#pragma unroll
    for (int s = 0; s < KS; s++) {
        unsigned a0, a1, a2, a3;
        ldsm_x4(abase + s * 32, a0, a1, a2, a3);
#pragma unroll
        for (int i = 0; i < NT; i++) {
            uint2 b = *(const uint2*)(WF + (((size_t)(ntile0 + i) * KS + s) * 32 + lane) * 4);
            hmma(c[i], a0, a1, a2, a3, b.x, b.y);
        }
    }
}

// smem-output variant (bridge only)
template<int NT, int KS>
__device__ __forceinline__ void hgemm(const __half* A, int astr,
                                      const __half* __restrict__ WF,
                                      int ntile0, float* outp, int ostr)
{
    float c[NT][4];
    hgemm_reg<NT, KS>(A, astr, WF, ntile0, c);
    const int lane = threadIdx.x & 31;
    const int gid = lane >> 2, tig = lane & 3;
#pragma unroll
    for (int i = 0; i < NT; i++) {
        int n = (ntile0 + i) * 8 + tig * 2;
        *(float2*)(outp + gid * ostr + n) = make_float2(c[i][0], c[i][1]);
        *(float2*)(outp + (gid + 8) * ostr + n) = make_float2(c[i][2], c[i][3]);
    }
}

#define STR_A  152
#define STR_B  264
#define STR_D  136
#define STR_C  132    // fp32 c-state row stride (2-way max bank conflict)
#define GST    520

__global__ void __launch_bounds__(NTHR, 1) rnn_kernel(
    const float* __restrict__ x,
    const float* __restrict__ brb, const float* __restrict__ fc1b,
    const float* __restrict__ fc2w, const float* __restrict__ fc2b,
    float* __restrict__ out)
{
    extern __shared__ char smraw[];
    __half* xs   = (__half*)smraw;                 //  8192 B
    __half* bufA = (__half*)(smraw + 8192);        // [2][16][152]   9728 B
    __half* bufB = (__half*)(smraw + 17920);       // [2][16][264]  16896 B
    __half* d0b  = (__half*)(smraw + 34816);       // [2][16][136]   8704 B
    __half* d1b  = (__half*)(smraw + 43520);       // [2][16][136]   8704 B
    float*  gbuf = (float*)(smraw + 52224);        // [16][520]     33280 B (bridge only)
    float*  fcz  = (float*)(smraw + 85504);        // [16][64]       4096 B
    float*  sgb  = (float*)(smraw + 89600);        // [2][512]       4096 B (GRU biases)
    float*  slb  = (float*)(smraw + 93696);        // [2][512]       4096 B (LSTM biases)
    float*  c0s  = (float*)(smraw + 97792);        // [16][132]      8448 B
    float*  c1s  = (float*)(smraw + 106240);       // [16][132]      8448 B  -> 114688 total

    const int tid = threadIdx.x;
    const int wid = tid >> 5;
    const int lane = tid & 31;
    const int gid = lane >> 2, tig = lane & 3;
    const int j0 = wid * 8 + tig * 2;              // this thread's 2 units
    const int b0 = blockIdx.x * BT;

    // init
    for (int i = tid; i < BT * 256; i += NTHR) {
        int r = i >> 8, q = i & 255;
        xs[i] = __float2half(x[(size_t)(b0 + r) * 256 + q]);
    }
    for (int i = tid; i < 2 * 16 * STR_A; i += NTHR) bufA[i] = __float2half(0.f);
    for (int i = tid; i < 2 * 16 * STR_B; i += NTHR) bufB[i] = __float2half(0.f);
    for (int i = tid; i < 1024; i += NTHR) { sgb[i] = g_gb[i]; }
    for (int i = tid; i < 512; i += NTHR) { slb[i] = g_b0[i]; slb[512 + i] = g_b1[i]; }
    for (int i = tid; i < 16 * STR_C; i += NTHR) { c0s[i] = 0.f; c1s[i] = 0.f; }
    if (tid < 64) {
        int r = tid >> 2, k = tid & 3;
        bufA[r * STR_A + 128 + k] = __float2half(x[(size_t)(b0 + r) * 256 + k]);
    }
    __syncthreads();

    const float* sb0 = slb;
    const float* sb1 = slb + 512;

    // ---------------- LSTM encoder: in-register combine, 2 syncs/step ----------------
    for (int t = 0; t < S; t++) {
        const int p = t & 1, np = p ^ 1;
        __half* A0  = bufA + p * 16 * STR_A;
        __half* A0n = bufA + np * 16 * STR_A;
        __half* Bp  = bufB + p * 16 * STR_B;
        __half* Bn  = bufB + np * 16 * STR_B;

        // phase 1: L0 GEMM + combine -> h0 into A0n and Bp[0:128]
        {
            float c4[4][4];
            hgemm_reg<4, 9>(A0, STR_A, g_wf_l0, wid * 4, c4);
            float hh[2][2];
#pragma unroll
            for (int rs = 0; rs < 2; rs++)
#pragma unroll
                for (int e = 0; e < 2; e++) {
                    int ix = rs * 2 + e;
                    int ci = (gid + rs * 8) * STR_C + j0 + e;
                    float ii = c4[0][ix] + sb0[j0 + e];
                    float ff = c4[1][ix] + sb0[128 + j0 + e];
                    float gg = c4[2][ix] + sb0[256 + j0 + e];
                    float oo = c4[3][ix] + sb0[384 + j0 + e];
                    float cc = sigm(ff) * c0s[ci] + sigm(ii) * fast_tanh(gg);
                    c0s[ci] = cc;
                    hh[rs][e] = sigm(oo) * fast_tanh(cc);
                }
            __half2 h0v = __floats2half2_rn(hh[0][0], hh[0][1]);
            __half2 h1v = __floats2half2_rn(hh[1][0], hh[1][1]);
            *(__half2*)(A0n + gid * STR_A + j0) = h0v;
            *(__half2*)(A0n + (gid + 8) * STR_A + j0) = h1v;
            *(__half2*)(Bp + gid * STR_B + j0) = h0v;
            *(__half2*)(Bp + (gid + 8) * STR_B + j0) = h1v;
            if (t < S - 1 && tid < 64) {
                int r = tid >> 2, k = tid & 3;
                A0n[r * STR_A + 128 + k] = xs[r * 256 + (t + 1) * 4 + k];
            }
        }
        __syncthreads();

        // phase 2: L1 GEMM (concat-K) + combine -> h1 into Bn[128:256]
        {
            float c4[4][4];
            hgemm_reg<4, 16>(Bp, STR_B, g_wf_l1, wid * 4, c4);
            float hh[2][2];
#pragma unroll
            for (int rs = 0; rs < 2; rs++)
#pragma unroll
                for (int e = 0; e < 2; e++) {
                    int ix = rs * 2 + e;
                    int ci = (gid + rs * 8) * STR_C + j0 + e;
                    float ii = c4[0][ix] + sb1[j0 + e];
                    float ff = c4[1][ix] + sb1[128 + j0 + e];
                    float gg = c4[2][ix] + sb1[256 + j0 + e];
                    float oo = c4[3][ix] + sb1[384 + j0 + e];
                    float cc = sigm(ff) * c1s[ci] + sigm(ii) * fast_tanh(gg);
                    c1s[ci] = cc;
                    hh[rs][e] = sigm(oo) * fast_tanh(cc);
                }
            *(__half2*)(Bn + gid * STR_B + 128 + j0) = __floats2half2_rn(hh[0][0], hh[0][1]);
            *(__half2*)(Bn + (gid + 8) * STR_B + 128 + j0) = __floats2half2_rn(hh[1][0], hh[1][1]);
        }
        __syncthreads();
    }
    __half* h0f = bufA;           // final h0 (buffer 0)
    __half* h1f = bufB + 128;     // final h1 (buffer 0, cols 128-255)

    // ---------------- bridge ----------------
    if (wid < 8) hgemm<2, 8>(h0f, STR_A, g_wf_br, wid * 2, gbuf, GST);
    else         hgemm<2, 8>(h1f, STR_B, g_wf_br, (wid - 8) * 2, gbuf + 128, GST);
    __syncthreads();
#pragma unroll
    for (int it = 0; it < 4; it++) {
        int idx = tid + it * NTHR;
        int r = idx >> 7, j = idx & 127;
        float bv = brb[j];
        d0b[r * STR_D + j] = __float2half(fast_tanh(gbuf[r * GST + j] + bv));
        d1b[r * STR_D + j] = __float2half(fast_tanh(gbuf[r * GST + 128 + j] + bv));
    }
    __syncthreads();

    const float* sgb0 = sgb;
    const float* sgb1 = sgb + 512;

    // ---------------- autoregressive GRU decode: in-register combine (R12) ----------------
    for (int t = 0; t < PRED; t++) {
        const int pg = t & 1, npg = pg ^ 1;
        __half* d0p = d0b + pg * 16 * STR_D;
        __half* d0n = d0b + npg * 16 * STR_D;
        __half* d1p = d1b + pg * 16 * STR_D;
        __half* d1n = d1b + npg * 16 * STR_D;
        const __half* A1 = (t == 0) ? h1f : d1p;
        const int a1str = (t == 0) ? STR_B : STR_D;

        // phase A: GRU L0 GEMMs + in-register combine -> d0n
        {
            float ai[3][4], ah[3][4];
            hgemm_reg<3, 8>(A1, a1str, g_wf_gi0, wid * 3, ai);
            hgemm_reg<3, 8>(d0p, STR_D, g_wf_gh0, wid * 3, ah);
            float val[2][2];
#pragma unroll
            for (int rs = 0; rs < 2; rs++)
#pragma unroll
                for (int e = 0; e < 2; e++) {
                    int ix = rs * 2 + e;
                    float rr = sigm(ai[0][ix] + ah[0][ix] + sgb0[j0 + e]);
                    float zz = sigm(ai[1][ix] + ah[1][ix] + sgb0[128 + j0 + e]);
                    float nn = fast_tanh(ai[2][ix] + sgb0[256 + j0 + e]
                                         + rr * (ah[2][ix] + sgb0[384 + j0 + e]));
                    float hold = __half2float(d0p[(gid + rs * 8) * STR_D + j0 + e]);
                    val[rs][e] = (1.f - zz) * nn + zz * hold;
                }
            *(__half2*)(d0n + gid * STR_D + j0) = __floats2half2_rn(val[0][0], val[0][1]);
            *(__half2*)(d0n + (gid + 8) * STR_D + j0) = __floats2half2_rn(val[1][0], val[1][1]);
        }
        __syncthreads();

        // phase B: GRU L1 GEMMs + in-register combine -> d1n
        {
            float ai[3][4], ah[3][4];
            hgemm_reg<3, 8>(d0n, STR_D, g_wf_gi1, wid * 3, ai);
            hgemm_reg<3, 8>(d1p, STR_D, g_wf_gh1, wid * 3, ah);
            float val[2][2];
#pragma unroll
            for (int rs = 0; rs < 2; rs++)
#pragma unroll
                for (int e = 0; e < 2; e++) {
                    int ix = rs * 2 + e;
                    float rr = sigm(ai[0][ix] + ah[0][ix] + sgb1[j0 + e]);
                    float zz = sigm(ai[1][ix] + ah[1][ix] + sgb1[128 + j0 + e]);
                    float nn = fast_tanh(ai[2][ix] + sgb1[256 + j0 + e]
                                         + rr * (ah[2][ix] + sgb1[384 + j0 + e]));
                    float hold = __half2float(d1p[(gid + rs * 8) * STR_D + j0 + e]);
                    val[rs][e] = (1.f - zz) * nn + zz * hold;
                }
            *(__half2*)(d1n + gid * STR_D + j0) = __floats2half2_rn(val[0][0], val[0][1]);
            *(__half2*)(d1n + (gid + 8) * STR_D + j0) = __floats2half2_rn(val[1][0], val[1][1]);
        }
        __syncthreads();

        // phase C: fc1 (relu) on d1n
#pragma unroll
        for (int half = 0; half < 2; half++) {
            int o = tid + half * NTHR;
            int r = o >> 6, c = o & 63;
            float acc = fc1b[c];
#pragma unroll 4
            for (int k = 0; k < 128; k += 2) {
                float2 fv = __half22float2(*(const __half2*)(d1n + r * STR_D + k));
                acc = fmaf(fv.x, g_wfc1[(k + 0) * 64 + c], acc);
                acc = fmaf(fv.y, g_wfc1[(k + 1) * 64 + c], acc);
            }
            fcz[r * 64 + c] = fmaxf(acc, 0.f);
        }
        __syncthreads();

        // phase D: fc2
        if (tid < 32) {
            int r = tid >> 1, cc = tid & 1;
            float s2 = fc2b[cc];
#pragma unroll
            for (int k = 0; k < 64; k++)
                s2 = fmaf(fcz[r * 64 + k], fc2w[cc * 64 + k], s2);
            out[(size_t)(b0 + r) * PRED * 2 + t * 2 + cc] = s2;
        }
        __syncthreads();
    }
}

extern "C" void kernel_launch(void* const* d_in, const int* in_sizes, int n_in,
                              void* d_out, int out_size)
{
    const float* p[24];
    int np = 0;
    for (int i = 0; i < n_in && np < 24; i++) {
        if (in_sizes[i] == 1) continue;
        p[np++] = (const float*)d_in[i];
    }
    const float* x = p[0];
    const float *lwih0 = p[1], *lwhh0 = p[2], *lbih0 = p[3], *lbhh0 = p[4];
    const float *lwih1 = p[5], *lwhh1 = p[6], *lbih1 = p[7], *lbhh1 = p[8];
    const float *gwi0 = p[9], *gwh0 = p[10], *gbi0 = p[11], *gbh0 = p[12];
    const float *gwi1 = p[13], *gwh1 = p[14], *gbi1 = p[15], *gbh1 = p[16];
    const float *brw = p[17], *brb = p[18];
    const float *fc1w = p[19], *fc1b = p[20];
    const float *fc2w = p[21], *fc2b = p[22];

    prep_kernel<<<512, 256>>>(lwih0, lwhh0, lbih0, lbhh0, lwih1, lwhh1, lbih1, lbhh1,
                              gwi0, gwh0, gbi0, gbh0, gwi1, gwh1, gbi1, gbh1,
                              brw, fc1w);

    const int smem = 114688;
    cudaFuncSetAttribute(rnn_kernel, cudaFuncAttributeMaxDynamicSharedMemorySize, smem);
    rnn_kernel<<<NBLK, NTHR, smem>>>(x, brb, fc1b, fc2w, fc2b, (float*)d_out);
}

// round 14
// speedup vs baseline: 2.3520x; 1.2004x over previous
#include <cuda_runtime.h>
#include <cuda_fp16.h>
#include <math.h>

#define H 128
#define S 64
#define PRED 50
#define BT 16
#define NBLK 128
#define NTHR 512

// ---------------- fragment-ordered weights, GATE-INTERLEAVED everywhere ----------------
__device__ __align__(16) __half g_wf_l0[64 * 9 * 128];    // LSTM L0: K=144 (128 h + 4 x + pad)
__device__ __align__(16) __half g_wf_l1[64 * 16 * 128];   // LSTM L1: K=256 (wih1|whh1)
__device__ __align__(16) __half g_wf_gi0[48 * 8 * 128];   // GRU, gate-interleaved
__device__ __align__(16) __half g_wf_gh0[48 * 8 * 128];
__device__ __align__(16) __half g_wf_gi1[48 * 8 * 128];
__device__ __align__(16) __half g_wf_gh1[48 * 8 * 128];
__device__ __align__(16) __half g_wf_br[16 * 8 * 128];    // bridge (natural)
__device__ __align__(16) float  g_b0[512];
__device__ __align__(16) float  g_b1[512];
__device__ __align__(16) float  g_gb[1024];
__device__ __align__(16) float  g_wfc1[128 * 64];         // [k][c] fp32

__global__ void prep_kernel(
    const float* __restrict__ lwih0, const float* __restrict__ lwhh0,
    const float* __restrict__ lbih0, const float* __restrict__ lbhh0,
    const float* __restrict__ lwih1, const float* __restrict__ lwhh1,
    const float* __restrict__ lbih1, const float* __restrict__ lbhh1,
    const float* __restrict__ gwi0, const float* __restrict__ gwh0,
    const float* __restrict__ gbi0, const float* __restrict__ gbh0,
    const float* __restrict__ gwi1, const float* __restrict__ gwh1,
    const float* __restrict__ gbi1, const float* __restrict__ gbh1,
    const float* __restrict__ brw, const float* __restrict__ fc1w)
{
    int i0 = blockIdx.x * blockDim.x + threadIdx.x;
    int st = gridDim.x * blockDim.x;

#define FRAG_DECODE(i, KS)                                  \
    int e = (i) & 3;                                        \
    int lane = ((i) >> 2) & 31;                             \
    int q2 = (i) >> 7;                                      \
    int s = q2 % (KS);                                      \
    int nt = q2 / (KS);                                     \
    int gid = lane >> 2;                                    \
    int k = s * 16 + (lane & 3) * 2 + (e & 1) + (e >> 1) * 8;

    for (int i = i0; i < 64 * 9 * 128; i += st) {
        FRAG_DECODE(i, 9);
        int n = (nt & 3) * 128 + (nt >> 2) * 8 + gid;
        float v = 0.f;
        if (k < 128)      v = lwhh0[n * 128 + k];
        else if (k < 132) v = lwih0[n * 4 + (k - 128)];
        g_wf_l0[i] = __float2half(v);
    }
    for (int i = i0; i < 64 * 16 * 128; i += st) {
        FRAG_DECODE(i, 16);
        int n = (nt & 3) * 128 + (nt >> 2) * 8 + gid;
        float v = (k < 128) ? lwih1[n * 128 + k] : lwhh1[n * 128 + (k - 128)];
        g_wf_l1[i] = __float2half(v);
    }
    for (int i = i0; i < 48 * 8 * 128; i += st) {
        FRAG_DECODE(i, 8);
        int n = (nt % 3) * 128 + (nt / 3) * 8 + gid;
        g_wf_gi0[i] = __float2half(gwi0[n * 128 + k]);
        g_wf_gh0[i] = __float2half(gwh0[n * 128 + k]);
        g_wf_gi1[i] = __float2half(gwi1[n * 128 + k]);
        g_wf_gh1[i] = __float2half(gwh1[n * 128 + k]);
    }
    for (int i = i0; i < 16 * 8 * 128; i += st) {
        FRAG_DECODE(i, 8);
        int n = nt * 8 + gid;
        g_wf_br[i] = __float2half(brw[n * 128 + k]);
    }
#undef FRAG_DECODE
    for (int i = i0; i < 512; i += st) {
        g_b0[i] = lbih0[i] + lbhh0[i];
        g_b1[i] = lbih1[i] + lbhh1[i];
    }
    for (int i = i0; i < 1024; i += st) {
        int l = i >> 9, q = i & 511;
        int reg = q >> 7, j = q & 127;
        const float* bi = l ? gbi1 : gbi0;
        const float* bh = l ? gbh1 : gbh0;
        float v;
        if (reg == 0)      v = bi[j] + bh[j];
        else if (reg == 1) v = bi[128 + j] + bh[128 + j];
        else if (reg == 2) v = bi[256 + j];
        else               v = bh[256 + j];
        g_gb[i] = v;
    }
    for (int i = i0; i < 128 * 64; i += st) {
        int k = i / 64, c = i % 64;
        g_wfc1[i] = fc1w[c * 128 + k];
    }
}

// MUFU activations: sigmoid via single tanh (sigma(x) = 0.5*tanh(x/2)+0.5)
__device__ __forceinline__ float fast_tanh(float x) {
    float y; asm("tanh.approx.f32 %0, %1;" : "=f"(y) : "f"(x)); return y;
}
__device__ __forceinline__ float sigm(float v) {
    return fmaf(0.5f, fast_tanh(0.5f * v), 0.5f);
}

__device__ __forceinline__ unsigned smem_u32(const void* p) {
    return (unsigned)__cvta_generic_to_shared(p);
}
__device__ __forceinline__ void ldsm_x4(unsigned addr, unsigned& r0, unsigned& r1,
                                        unsigned& r2, unsigned& r3) {
    asm volatile("ldmatrix.sync.aligned.m8n8.x4.shared.b16 {%0,%1,%2,%3}, [%4];\n"
                 : "=r"(r0), "=r"(r1), "=r"(r2), "=r"(r3) : "r"(addr));
}
__device__ __forceinline__ void hmma(float* c, unsigned a0, unsigned a1, unsigned a2,
                                     unsigned a3, unsigned b0, unsigned b1) {
    asm volatile("mma.sync.aligned.m16n8k16.row.col.f32.f16.f16.f32 "
                 "{%0,%1,%2,%3}, {%4,%5,%6,%7}, {%8,%9}, {%0,%1,%2,%3};\n"
                 : "+f"(c[0]), "+f"(c[1]), "+f"(c[2]), "+f"(c[3])
                 : "r"(a0), "r"(a1), "r"(a2), "r"(a3), "r"(b0), "r"(b1));
}

// register-accumulator warp GEMM
template<int NT, int KS>
__device__ __forceinline__ void hgemm_reg(const __half* A, int astr,
                                          const __half* __restrict__ WF,
                                          int ntile0, float (&c)[NT][4])
{
    const int lane = threadIdx.x & 31;
    unsigned abase = smem_u32(A) + (unsigned)(((lane & 15) * astr + ((lane >> 4) << 3)) * 2);
#pragma unroll
    for (int i = 0; i < NT; i++) { c[i][0] = c[i][1] = c[i][2] = c[i][3] = 0.f; }
#pragma unroll
    for (int s = 0; s < KS; s++) {
        unsigned a0, a1, a2, a3;
        ldsm_x4(abase + s * 32, a0, a1, a2, a3);
#pragma unroll
        for (int i = 0; i < NT; i++) {
            uint2 b = *(const uint2*)(WF + (((size_t)(ntile0 + i) * KS + s) * 32 + lane) * 4);
            hmma(c[i], a0, a1, a2, a3, b.x, b.y);
        }
    }
}

// smem-output variant (bridge only)
template<int NT, int KS>
__device__ __forceinline__ void hgemm(const __half* A, int astr,
                                      const __half* __restrict__ WF,
                                      int ntile0, float* outp, int ostr)
{
    float c[NT][4];
    hgemm_reg<NT, KS>(A, astr, WF, ntile0, c);
    const int lane = threadIdx.x & 31;
    const int gid = lane >> 2, tig = lane & 3;
#pragma unroll
    for (int i = 0; i < NT; i++) {
        int n = (ntile0 + i) * 8 + tig * 2;
        *(float2*)(outp + gid * ostr + n) = make_float2(c[i][0], c[i][1]);
        *(float2*)(outp + (gid + 8) * ostr + n) = make_float2(c[i][2], c[i][3]);
    }
}

#define STR_A  152
#define STR_B  264
#define STR_D  136
#define STR_C  132
#define GST    520

__global__ void __launch_bounds__(NTHR, 1) rnn_kernel(
    const float* __restrict__ x,
    const float* __restrict__ brb, const float* __restrict__ fc1b,
    const float* __restrict__ fc2w, const float* __restrict__ fc2b,
    float* __restrict__ out)
{
    extern __shared__ char smraw[];
    __half* xs   = (__half*)smraw;                 //  8192 B
    __half* bufA = (__half*)(smraw + 8192);        // [2][16][152]   9728 B
    __half* bufB = (__half*)(smraw + 17920);       // [2][16][264]  16896 B
    __half* d0b  = (__half*)(smraw + 34816);       // [2][16][136]   8704 B
    __half* d1b  = (__half*)(smraw + 43520);       // [2][16][136]   8704 B
    float*  gbuf = (float*)(smraw + 52224);        // [16][520]     33280 B (bridge; then fc1w cache)
    float*  fcw2 = (float*)(smraw + 85504);        // fc2w(128) + fc1b(64)   4096 B
    float*  sgb  = (float*)(smraw + 89600);        // [2][512]       4096 B (GRU biases)
    float*  slb  = (float*)(smraw + 93696);        // [2][512]       4096 B (LSTM biases)
    float*  c0s  = (float*)(smraw + 97792);        // [16][132]      8448 B
    float*  c1s  = (float*)(smraw + 106240);       // [16][132]      8448 B  -> 114688 total

    const int tid = threadIdx.x;
    const int wid = tid >> 5;
    const int lane = tid & 31;
    const int gid = lane >> 2, tig = lane & 3;
    const int j0 = wid * 8 + tig * 2;
    const int b0 = blockIdx.x * BT;

    // init
    for (int i = tid; i < BT * 256; i += NTHR) {
        int r = i >> 8, q = i & 255;
        xs[i] = __float2half(x[(size_t)(b0 + r) * 256 + q]);
    }
    for (int i = tid; i < 2 * 16 * STR_A; i += NTHR) bufA[i] = __float2half(0.f);
    for (int i = tid; i < 2 * 16 * STR_B; i += NTHR) bufB[i] = __float2half(0.f);
    for (int i = tid; i < 1024; i += NTHR) { sgb[i] = g_gb[i]; }
    for (int i = tid; i < 512; i += NTHR) { slb[i] = g_b0[i]; slb[512 + i] = g_b1[i]; }
    for (int i = tid; i < 16 * STR_C; i += NTHR) { c0s[i] = 0.f; c1s[i] = 0.f; }
    if (tid < 64) {
        int r = tid >> 2, k = tid & 3;
        bufA[r * STR_A + 128 + k] = __float2half(x[(size_t)(b0 + r) * 256 + k]);
    }
    __syncthreads();

    const float* sb0 = slb;
    const float* sb1 = slb + 512;

    // ---------------- LSTM encoder: in-register combine, 2 syncs/step ----------------
    for (int t = 0; t < S; t++) {
        const int p = t & 1, np = p ^ 1;
        __half* A0  = bufA + p * 16 * STR_A;
        __half* A0n = bufA + np * 16 * STR_A;
        __half* Bp  = bufB + p * 16 * STR_B;
        __half* Bn  = bufB + np * 16 * STR_B;

        {
            float c4[4][4];
            hgemm_reg<4, 9>(A0, STR_A, g_wf_l0, wid * 4, c4);
            float hh[2][2];
#pragma unroll
            for (int rs = 0; rs < 2; rs++)
#pragma unroll
                for (int e = 0; e < 2; e++) {
                    int ix = rs * 2 + e;
                    int ci = (gid + rs * 8) * STR_C + j0 + e;
                    float ii = c4[0][ix] + sb0[j0 + e];
                    float ff = c4[1][ix] + sb0[128 + j0 + e];
                    float gg = c4[2][ix] + sb0[256 + j0 + e];
                    float oo = c4[3][ix] + sb0[384 + j0 + e];
                    float cc = sigm(ff) * c0s[ci] + sigm(ii) * fast_tanh(gg);
                    c0s[ci] = cc;
                    hh[rs][e] = sigm(oo) * fast_tanh(cc);
                }
            __half2 h0v = __floats2half2_rn(hh[0][0], hh[0][1]);
            __half2 h1v = __floats2half2_rn(hh[1][0], hh[1][1]);
            *(__half2*)(A0n + gid * STR_A + j0) = h0v;
            *(__half2*)(A0n + (gid + 8) * STR_A + j0) = h1v;
            *(__half2*)(Bp + gid * STR_B + j0) = h0v;
            *(__half2*)(Bp + (gid + 8) * STR_B + j0) = h1v;
            if (t < S - 1 && tid < 64) {
                int r = tid >> 2, k = tid & 3;
                A0n[r * STR_A + 128 + k] = xs[r * 256 + (t + 1) * 4 + k];
            }
        }
        __syncthreads();

        {
            float c4[4][4];
            hgemm_reg<4, 16>(Bp, STR_B, g_wf_l1, wid * 4, c4);
            float hh[2][2];
#pragma unroll
            for (int rs = 0; rs < 2; rs++)
#pragma unroll
                for (int e = 0; e < 2; e++) {
                    int ix = rs * 2 + e;
                    int ci = (gid + rs * 8) * STR_C + j0 + e;
                    float ii = c4[0][ix] + sb1[j0 + e];
                    float ff = c4[1][ix] + sb1[128 + j0 + e];
                    float gg = c4[2][ix] + sb1[256 + j0 + e];
                    float oo = c4[3][ix] + sb1[384 + j0 + e];
                    float cc = sigm(ff) * c1s[ci] + sigm(ii) * fast_tanh(gg);
                    c1s[ci] = cc;
                    hh[rs][e] = sigm(oo) * fast_tanh(cc);
                }
            *(__half2*)(Bn + gid * STR_B + 128 + j0) = __floats2half2_rn(hh[0][0], hh[0][1]);
            *(__half2*)(Bn + (gid + 8) * STR_B + 128 + j0) = __floats2half2_rn(hh[1][0], hh[1][1]);
        }
        __syncthreads();
    }
    __half* h0f = bufA;           // final h0 (buffer 0)
    __half* h1f = bufB + 128;     // final h1 (buffer 0, cols 128-255)

    // ---------------- bridge ----------------
    if (wid < 8) hgemm<2, 8>(h0f, STR_A, g_wf_br, wid * 2, gbuf, GST);
    else         hgemm<2, 8>(h1f, STR_B, g_wf_br, (wid - 8) * 2, gbuf + 128, GST);
    __syncthreads();
#pragma unroll
    for (int it = 0; it < 4; it++) {
        int idx = tid + it * NTHR;
        int r = idx >> 7, j = idx & 127;
        float bv = brb[j];
        d0b[r * STR_D + j] = __float2half(fast_tanh(gbuf[r * GST + j] + bv));
        d1b[r * STR_D + j] = __float2half(fast_tanh(gbuf[r * GST + 128 + j] + bv));
    }
    __syncthreads();

    // cache fc1 weights (32 KB) into gbuf (dead after bridge), fc2w+fc1b into fcw2
    for (int i = tid; i < 128 * 64; i += NTHR) gbuf[i] = g_wfc1[i];
    for (int i = tid; i < 128; i += NTHR) fcw2[i] = fc2w[i];
    for (int i = tid; i < 64; i += NTHR) fcw2[128 + i] = fc1b[i];
    __syncthreads();

    const float* sgb0 = sgb;
    const float* sgb1 = sgb + 512;

    // ---------------- GRU decode: 2 syncs/step, head is barrier-free ----------------
    for (int t = 0; t < PRED; t++) {
        const int pg = t & 1, npg = pg ^ 1;
        __half* d0p = d0b + pg * 16 * STR_D;
        __half* d0n = d0b + npg * 16 * STR_D;
        __half* d1p = d1b + pg * 16 * STR_D;
        __half* d1n = d1b + npg * 16 * STR_D;
        const __half* A1 = (t == 0) ? h1f : d1p;
        const int a1str = (t == 0) ? STR_B : STR_D;

        // phase A: GRU L0 GEMMs + in-register combine -> d0n
        {
            float ai[3][4], ah[3][4];
            hgemm_reg<3, 8>(A1, a1str, g_wf_gi0, wid * 3, ai);
            hgemm_reg<3, 8>(d0p, STR_D, g_wf_gh0, wid * 3, ah);
            float val[2][2];
#pragma unroll
            for (int rs = 0; rs < 2; rs++)
#pragma unroll
                for (int e = 0; e < 2; e++) {
                    int ix = rs * 2 + e;
                    float rr = sigm(ai[0][ix] + ah[0][ix] + sgb0[j0 + e]);
                    float zz = sigm(ai[1][ix] + ah[1][ix] + sgb0[128 + j0 + e]);
                    float nn = fast_tanh(ai[2][ix] + sgb0[256 + j0 + e]
                                         + rr * (ah[2][ix] + sgb0[384 + j0 + e]));
                    float hold = __half2float(d0p[(gid + rs * 8) * STR_D + j0 + e]);
                    val[rs][e] = (1.f - zz) * nn + zz * hold;
                }
            *(__half2*)(d0n + gid * STR_D + j0) = __floats2half2_rn(val[0][0], val[0][1]);
            *(__half2*)(d0n + (gid + 8) * STR_D + j0) = __floats2half2_rn(val[1][0], val[1][1]);
        }
        __syncthreads();

        // phase B: GRU L1 GEMMs + in-register combine -> d1n
        {
            float ai[3][4], ah[3][4];
            hgemm_reg<3, 8>(d0n, STR_D, g_wf_gi1, wid * 3, ai);
            hgemm_reg<3, 8>(d1p, STR_D, g_wf_gh1, wid * 3, ah);
            float val[2][2];
#pragma unroll
            for (int rs = 0; rs < 2; rs++)
#pragma unroll
                for (int e = 0; e < 2; e++) {
                    int ix = rs * 2 + e;
                    float rr = sigm(ai[0][ix] + ah[0][ix] + sgb1[j0 + e]);
                    float zz = sigm(ai[1][ix] + ah[1][ix] + sgb1[128 + j0 + e]);
                    float nn = fast_tanh(ai[2][ix] + sgb1[256 + j0 + e]
                                         + rr * (ah[2][ix] + sgb1[384 + j0 + e]));
                    float hold = __half2float(d1p[(gid + rs * 8) * STR_D + j0 + e]);
                    val[rs][e] = (1.f - zz) * nn + zz * hold;
                }
            *(__half2*)(d1n + gid * STR_D + j0) = __floats2half2_rn(val[0][0], val[0][1]);
            *(__half2*)(d1n + (gid + 8) * STR_D + j0) = __floats2half2_rn(val[1][0], val[1][1]);
        }
        __syncthreads();

        // head (barrier-free): warp w owns row w. fc1 2 cols/lane from smem weights,
        // fc2 via warp-shuffle reduction. Reads only d1n (stable until B(t+1)).
        {
            const __half* drow = d1n + wid * STR_D;
            float a0 = fcw2[128 + 2 * lane];       // fc1b
            float a1 = fcw2[128 + 2 * lane + 1];
#pragma unroll 4
            for (int k = 0; k < 128; k += 2) {
                float2 f = __half22float2(*(const __half2*)(drow + k));
                float2 w0 = *(const float2*)(gbuf + k * 64 + 2 * lane);
                float2 w1 = *(const float2*)(gbuf + (k + 1) * 64 + 2 * lane);
                a0 = fmaf(f.x, w0.x, a0); a0 = fmaf(f.y, w1.x, a0);
                a1 = fmaf(f.x, w0.y, a1); a1 = fmaf(f.y, w1.y, a1);
            }
            a0 = fmaxf(a0, 0.f); a1 = fmaxf(a1, 0.f);
            float s0 = a0 * fcw2[2 * lane]      + a1 * fcw2[2 * lane + 1];
            float s1 = a0 * fcw2[64 + 2 * lane] + a1 * fcw2[64 + 2 * lane + 1];
#pragma unroll
            for (int off = 16; off; off >>= 1) {
                s0 += __shfl_xor_sync(0xFFFFFFFFu, s0, off);
                s1 += __shfl_xor_sync(0xFFFFFFFFu, s1, off);
            }
            if (lane == 0) {
                float* op = out + (size_t)(b0 + wid) * PRED * 2 + t * 2;
                op[0] = s0 + fc2b[0];
                op[1] = s1 + fc2b[1];
            }
        }
    }
}

extern "C" void kernel_launch(void* const* d_in, const int* in_sizes, int n_in,
                              void* d_out, int out_size)
{
    const float* p[24];
    int np = 0;
    for (int i = 0; i < n_in && np < 24; i++) {
        if (in_sizes[i] == 1) continue;
        p[np++] = (const float*)d_in[i];
    }
    const float* x = p[0];
    const float *lwih0 = p[1], *lwhh0 = p[2], *lbih0 = p[3], *lbhh0 = p[4];
    const float *lwih1 = p[5], *lwhh1 = p[6], *lbih1 = p[7], *lbhh1 = p[8];
    const float *gwi0 = p[9], *gwh0 = p[10], *gbi0 = p[11], *gbh0 = p[12];
    const float *gwi1 = p[13], *gwh1 = p[14], *gbi1 = p[15], *gbh1 = p[16];
    const float *brw = p[17], *brb = p[18];
    const float *fc1w = p[19], *fc1b = p[20];
    const float *fc2w = p[21], *fc2b = p[22];

    prep_kernel<<<512, 256>>>(lwih0, lwhh0, lbih0, lbhh0, lwih1, lwhh1, lbih1, lbhh1,
                              gwi0, gwh0, gbi0, gbh0, gwi1, gwh1, gbi1, gbh1,
                              brw, fc1w);

    const int smem = 114688;
    cudaFuncSetAttribute(rnn_kernel, cudaFuncAttributeMaxDynamicSharedMemorySize, smem);
    rnn_kernel<<<NBLK, NTHR, smem>>>(x, brb, fc1b, fc2w, fc2b, (float*)d_out);
}

// round 16
// speedup vs baseline: 2.4719x; 1.0510x over previous
#include <cuda_runtime.h>
#include <cuda_fp16.h>
#include <math.h>

#define H 128
#define S 64
#define PRED 50
#define BT 16
#define NBLK 128
#define NTHR 512

// ---------------- fragment-ordered weights ----------------
// LSTM (warp-specialized): warp w8 (0-7) owns tiles nt = w8*8 + g*2 + u holding
// gate g of units [w8*16 + u*8, +8). GRU: nt%3 gate-interleave (R13). Bridge natural.
__device__ __align__(16) __half g_wf_l0[64 * 9 * 128];    // LSTM L0: K=144
__device__ __align__(16) __half g_wf_l1[64 * 16 * 128];   // LSTM L1: K=256
__device__ __align__(16) __half g_wf_gi0[48 * 8 * 128];
__device__ __align__(16) __half g_wf_gh0[48 * 8 * 128];
__device__ __align__(16) __half g_wf_gi1[48 * 8 * 128];
__device__ __align__(16) __half g_wf_gh1[48 * 8 * 128];
__device__ __align__(16) __half g_wf_br[16 * 8 * 128];
__device__ __align__(16) float  g_b0[512];
__device__ __align__(16) float  g_b1[512];
__device__ __align__(16) float  g_gb[1024];
__device__ __align__(16) float  g_wfc1[128 * 64];

__global__ void prep_kernel(
    const float* __restrict__ lwih0, const float* __restrict__ lwhh0,
    const float* __restrict__ lbih0, const float* __restrict__ lbhh0,
    const float* __restrict__ lwih1, const float* __restrict__ lwhh1,
    const float* __restrict__ lbih1, const float* __restrict__ lbhh1,
    const float* __restrict__ gwi0, const float* __restrict__ gwh0,
    const float* __restrict__ gbi0, const float* __restrict__ gbh0,
    const float* __restrict__ gwi1, const float* __restrict__ gwh1,
    const float* __restrict__ gbi1, const float* __restrict__ gbh1,
    const float* __restrict__ brw, const float* __restrict__ fc1w)
{
    int i0 = blockIdx.x * blockDim.x + threadIdx.x;
    int st = gridDim.x * blockDim.x;

#define FRAG_DECODE(i, KS)                                  \
    int e = (i) & 3;                                        \
    int lane = ((i) >> 2) & 31;                             \
    int q2 = (i) >> 7;                                      \
    int s = q2 % (KS);                                      \
    int nt = q2 / (KS);                                     \
    int gid = lane >> 2;                                    \
    int k = s * 16 + (lane & 3) * 2 + (e & 1) + (e >> 1) * 8;

    // LSTM: nt = w8*8 + g*2 + u  ->  n = g*128 + w8*16 + u*8 + gid
    for (int i = i0; i < 64 * 9 * 128; i += st) {
        FRAG_DECODE(i, 9);
        int w8 = nt >> 3, g = (nt >> 1) & 3, u = nt & 1;
        int n = g * 128 + w8 * 16 + u * 8 + gid;
        float v = 0.f;
        if (k < 128)      v = lwhh0[n * 128 + k];
        else if (k < 132) v = lwih0[n * 4 + (k - 128)];
        g_wf_l0[i] = __float2half(v);
    }
    for (int i = i0; i < 64 * 16 * 128; i += st) {
        FRAG_DECODE(i, 16);
        int w8 = nt >> 3, g = (nt >> 1) & 3, u = nt & 1;
        int n = g * 128 + w8 * 16 + u * 8 + gid;
        float v = (k < 128) ? lwih1[n * 128 + k] : lwhh1[n * 128 + (k - 128)];
        g_wf_l1[i] = __float2half(v);
    }
    for (int i = i0; i < 48 * 8 * 128; i += st) {
        FRAG_DECODE(i, 8);
        int n = (nt % 3) * 128 + (nt / 3) * 8 + gid;
        g_wf_gi0[i] = __float2half(gwi0[n * 128 + k]);
        g_wf_gh0[i] = __float2half(gwh0[n * 128 + k]);
        g_wf_gi1[i] = __float2half(gwi1[n * 128 + k]);
        g_wf_gh1[i] = __float2half(gwh1[n * 128 + k]);
    }
    for (int i = i0; i < 16 * 8 * 128; i += st) {
        FRAG_DECODE(i, 8);
        int n = nt * 8 + gid;
        g_wf_br[i] = __float2half(brw[n * 128 + k]);
    }
#undef FRAG_DECODE
    for (int i = i0; i < 512; i += st) {
        g_b0[i] = lbih0[i] + lbhh0[i];
        g_b1[i] = lbih1[i] + lbhh1[i];
    }
    for (int i = i0; i < 1024; i += st) {
        int l = i >> 9, q = i & 511;
        int reg = q >> 7, j = q & 127;
        const float* bi = l ? gbi1 : gbi0;
        const float* bh = l ? gbh1 : gbh0;
        float v;
        if (reg == 0)      v = bi[j] + bh[j];
        else if (reg == 1) v = bi[128 + j] + bh[128 + j];
        else if (reg == 2) v = bi[256 + j];
        else               v = bh[256 + j];
        g_gb[i] = v;
    }
    for (int i = i0; i < 128 * 64; i += st) {
        int k = i / 64, c = i % 64;
        g_wfc1[i] = fc1w[c * 128 + k];
    }
}

__device__ __forceinline__ float fast_tanh(float x) {
    float y; asm("tanh.approx.f32 %0, %1;" : "=f"(y) : "f"(x)); return y;
}
__device__ __forceinline__ float sigm(float v) {
    return fmaf(0.5f, fast_tanh(0.5f * v), 0.5f);
}

__device__ __forceinline__ unsigned smem_u32(const void* p) {
    return (unsigned)__cvta_generic_to_shared(p);
}
__device__ __forceinline__ void ldsm_x4(unsigned addr, unsigned& r0, unsigned& r1,
                                        unsigned& r2, unsigned& r3) {
    asm volatile("ldmatrix.sync.aligned.m8n8.x4.shared.b16 {%0,%1,%2,%3}, [%4];\n"
                 : "=r"(r0), "=r"(r1), "=r"(r2), "=r"(r3) : "r"(addr));
}
__device__ __forceinline__ void hmma(float* c, unsigned a0, unsigned a1, unsigned a2,
                                     unsigned a3, unsigned b0, unsigned b1) {
    asm volatile("mma.sync.aligned.m16n8k16.row.col.f32.f16.f16.f32 "
                 "{%0,%1,%2,%3}, {%4,%5,%6,%7}, {%8,%9}, {%0,%1,%2,%3};\n"
                 : "+f"(c[0]), "+f"(c[1]), "+f"(c[2]), "+f"(c[3])
                 : "r"(a0), "r"(a1), "r"(a2), "r"(a3), "r"(b0), "r"(b1));
}

template<int NT, int KS>
__device__ __forceinline__ void hgemm_reg(const __half* A, int astr,
                                          const __half* __restrict__ WF,
                                          int ntile0, float (&c)[NT][4])
{
    const int lane = threadIdx.x & 31;
    unsigned abase = smem_u32(A) + (unsigned)(((lane & 15) * astr + ((lane >> 4) << 3)) * 2);
#pragma unroll
    for (int i = 0; i < NT; i++) { c[i][0] = c[i][1] = c[i][2] = c[i][3] = 0.f; }
#pragma unroll
    for (int s = 0; s < KS; s++) {
        unsigned a0, a1, a2, a3;
        ldsm_x4(abase + s * 32, a0, a1, a2, a3);
#pragma unroll
        for (int i = 0; i < NT; i++) {
            uint2 b = *(const uint2*)(WF + (((size_t)(ntile0 + i) * KS + s) * 32 + lane) * 4);
            hmma(c[i], a0, a1, a2, a3, b.x, b.y);
        }
    }
}

template<int NT, int KS>
__device__ __forceinline__ void hgemm(const __half* A, int astr,
                                      const __half* __restrict__ WF,
                                      int ntile0, float* outp, int ostr)
{
    float c[NT][4];
    hgemm_reg<NT, KS>(A, astr, WF, ntile0, c);
    const int lane = threadIdx.x & 31;
    const int gid = lane >> 2, tig = lane & 3;
#pragma unroll
    for (int i = 0; i < NT; i++) {
        int n = (ntile0 + i) * 8 + tig * 2;
        *(float2*)(outp + gid * ostr + n) = make_float2(c[i][0], c[i][1]);
        *(float2*)(outp + (gid + 8) * ostr + n) = make_float2(c[i][2], c[i][3]);
    }
}

#define STR_A  152
#define STR_B  264
#define STR_D  136
#define STR_C  132
#define GST    520

__global__ void __launch_bounds__(NTHR, 1) rnn_kernel(
    const float* __restrict__ x,
    const float* __restrict__ brb, const float* __restrict__ fc1b,
    const float* __restrict__ fc2w, const float* __restrict__ fc2b,
    float* __restrict__ out)
{
    extern __shared__ char smraw[];
    __half* xs   = (__half*)smraw;                 //  8192 B
    __half* bufA = (__half*)(smraw + 8192);        // [2][16][152]   9728 B
    __half* bufB = (__half*)(smraw + 17920);       // [2][16][264]  16896 B
    __half* d0b  = (__half*)(smraw + 34816);       // [2][16][136]   8704 B
    __half* d1b  = (__half*)(smraw + 43520);       // [2][16][136]   8704 B
    float*  gbuf = (float*)(smraw + 52224);        // [16][520]     33280 B (bridge; then fc1w cache)
    float*  fcw2 = (float*)(smraw + 85504);        // fc2w(128)+fc1b(64)  4096 B
    float*  sgb  = (float*)(smraw + 89600);        // [2][512]       4096 B
    float*  slb  = (float*)(smraw + 93696);        // [2][512]       4096 B
    float*  c0s  = (float*)(smraw + 97792);        // [16][132]      8448 B
    float*  c1s  = (float*)(smraw + 106240);       // [16][132]      8448 B -> 114688

    const int tid = threadIdx.x;
    const int wid = tid >> 5;
    const int lane = tid & 31;
    const int gid = lane >> 2, tig = lane & 3;
    const int grp = wid >> 3;          // LSTM: 0 -> L0, 1 -> L1
    const int w8 = wid & 7;
    const int j0 = wid * 8 + tig * 2;  // GRU unit mapping (R13)
    const int b0 = blockIdx.x * BT;

    // init
    for (int i = tid; i < BT * 256; i += NTHR) {
        int r = i >> 8, q = i & 255;
        xs[i] = __float2half(x[(size_t)(b0 + r) * 256 + q]);
    }
    for (int i = tid; i < 2 * 16 * STR_A; i += NTHR) bufA[i] = __float2half(0.f);
    for (int i = tid; i < 2 * 16 * STR_B; i += NTHR) bufB[i] = __float2half(0.f);
    for (int i = tid; i < 1024; i += NTHR) { sgb[i] = g_gb[i]; }
    for (int i = tid; i < 512; i += NTHR) { slb[i] = g_b0[i]; slb[512 + i] = g_b1[i]; }
    for (int i = tid; i < 16 * STR_C; i += NTHR) { c0s[i] = 0.f; c1s[i] = 0.f; }
    if (tid < 64) {
        int r = tid >> 2, k = tid & 3;
        bufA[r * STR_A + 128 + k] = __float2half(x[(size_t)(b0 + r) * 256 + k]);
    }
    __syncthreads();

    const float* sb0 = slb;
    const float* sb1 = slb + 512;

    // ---------------- LSTM encoder: warp-specialized layer pipeline, 1 sync/superphase ----------------
    // superphase s: warps 0-7 compute h0(s) (s<S); warps 8-15 compute h1(s-1) (s>0).
    for (int s = 0; s <= S; s++) {
        const int p = s & 1, np = p ^ 1;
        __half* A0  = bufA + p * 16 * STR_A;
        __half* A0n = bufA + np * 16 * STR_A;
        __half* Bp  = bufB + p * 16 * STR_B;
        __half* Bn  = bufB + np * 16 * STR_B;

        if (grp == 0) {
            if (s < S) {
                float c8[8][4];
                hgemm_reg<8, 9>(A0, STR_A, g_wf_l0, w8 * 8, c8);
#pragma unroll
                for (int u = 0; u < 2; u++) {
                    const int jb = w8 * 16 + u * 8 + tig * 2;
                    float hh[2][2];
#pragma unroll
                    for (int rs = 0; rs < 2; rs++)
#pragma unroll
                        for (int e = 0; e < 2; e++) {
                            int ix = rs * 2 + e;
                            int j = jb + e;
                            int ci = (gid + rs * 8) * STR_C + j;
                            float ii = c8[0 + u][ix] + sb0[j];
                            float ff = c8[2 + u][ix] + sb0[128 + j];
                            float gg = c8[4 + u][ix] + sb0[256 + j];
                            float oo = c8[6 + u][ix] + sb0[384 + j];
                            float cc = sigm(ff) * c0s[ci] + sigm(ii) * fast_tanh(gg);
                            c0s[ci] = cc;
                            hh[rs][e] = sigm(oo) * fast_tanh(cc);
                        }
                    __half2 h0v = __floats2half2_rn(hh[0][0], hh[0][1]);
                    __half2 h1v = __floats2half2_rn(hh[1][0], hh[1][1]);
                    *(__half2*)(A0n + gid * STR_A + jb) = h0v;
                    *(__half2*)(A0n + (gid + 8) * STR_A + jb) = h1v;
                    *(__half2*)(Bn + gid * STR_B + jb) = h0v;
                    *(__half2*)(Bn + (gid + 8) * STR_B + jb) = h1v;
                }
                if (s < S - 1 && tid < 64) {    // warps 0-1 (group 0): prefetch x(s+1)
                    int r = tid >> 2, k = tid & 3;
                    A0n[r * STR_A + 128 + k] = xs[r * 256 + (s + 1) * 4 + k];
                }
            }
        } else {
            if (s > 0) {
                float c8[8][4];
                hgemm_reg<8, 16>(Bp, STR_B, g_wf_l1, w8 * 8, c8);
#pragma unroll
                for (int u = 0; u < 2; u++) {
                    const int jb = w8 * 16 + u * 8 + tig * 2;
                    float hh[2][2];
#pragma unroll
                    for (int rs = 0; rs < 2; rs++)
#pragma unroll
                        for (int e = 0; e < 2; e++) {
                            int ix = rs * 2 + e;
                            int j = jb + e;
                            int ci = (gid + rs * 8) * STR_C + j;
                            float ii = c8[0 + u][ix] + sb1[j];
                            float ff = c8[2 + u][ix] + sb1[128 + j];
                            float gg = c8[4 + u][ix] + sb1[256 + j];
                            float oo = c8[6 + u][ix] + sb1[384 + j];
                            float cc = sigm(ff) * c1s[ci] + sigm(ii) * fast_tanh(gg);
                            c1s[ci] = cc;
                            hh[rs][e] = sigm(oo) * fast_tanh(cc);
                        }
                    *(__half2*)(Bn + gid * STR_B + 128 + jb) = __floats2half2_rn(hh[0][0], hh[0][1]);
                    *(__half2*)(Bn + (gid + 8) * STR_B + 128 + jb) = __floats2half2_rn(hh[1][0], hh[1][1]);
                }
            }
        }
        __syncthreads();
    }
    __half* h0f = bufA;                         // h0(63): buffer 0
    __half* h1f = bufB + 16 * STR_B + 128;      // h1(63): buffer 1, cols 128-255

    // ---------------- bridge ----------------
    if (wid < 8) hgemm<2, 8>(h0f, STR_A, g_wf_br, wid * 2, gbuf, GST);
    else         hgemm<2, 8>(h1f, STR_B, g_wf_br, (wid - 8) * 2, gbuf + 128, GST);
    __syncthreads();
#pragma unroll
    for (int it = 0; it < 4; it++) {
        int idx = tid + it * NTHR;
        int r = idx >> 7, j = idx & 127;
        float bv = brb[j];
        d0b[r * STR_D + j] = __float2half(fast_tanh(gbuf[r * GST + j] + bv));
        d1b[r * STR_D + j] = __float2half(fast_tanh(gbuf[r * GST + 128 + j] + bv));
    }
    __syncthreads();

    // cache fc1 weights into gbuf (dead after bridge), fc2w+fc1b into fcw2
    for (int i = tid; i < 128 * 64; i += NTHR) gbuf[i] = g_wfc1[i];
    for (int i = tid; i < 128; i += NTHR) fcw2[i] = fc2w[i];
    for (int i = tid; i < 64; i += NTHR) fcw2[128 + i] = fc1b[i];
    __syncthreads();

    const float* sgb0 = sgb;
    const float* sgb1 = sgb + 512;

    // ---------------- GRU decode: 2 syncs/step + barrier-free head (R14) ----------------
    for (int t = 0; t < PRED; t++) {
        const int pg = t & 1, npg = pg ^ 1;
        __half* d0p = d0b + pg * 16 * STR_D;
        __half* d0n = d0b + npg * 16 * STR_D;
        __half* d1p = d1b + pg * 16 * STR_D;
        __half* d1n = d1b + npg * 16 * STR_D;
        const __half* A1 = (t == 0) ? h1f : d1p;
        const int a1str = (t == 0) ? STR_B : STR_D;

        {
            float ai[3][4], ah[3][4];
            hgemm_reg<3, 8>(A1, a1str, g_wf_gi0, wid * 3, ai);
            hgemm_reg<3, 8>(d0p, STR_D, g_wf_gh0, wid * 3, ah);
            float val[2][2];
#pragma unroll
            for (int rs = 0; rs < 2; rs++)
#pragma unroll
                for (int e = 0; e < 2; e++) {
                    int ix = rs * 2 + e;
                    float rr = sigm(ai[0][ix] + ah[0][ix] + sgb0[j0 + e]);
                    float zz = sigm(ai[1][ix] + ah[1][ix] + sgb0[128 + j0 + e]);
                    float nn = fast_tanh(ai[2][ix] + sgb0[256 + j0 + e]
                                         + rr * (ah[2][ix] + sgb0[384 + j0 + e]));
                    float hold = __half2float(d0p[(gid + rs * 8) * STR_D + j0 + e]);
                    val[rs][e] = (1.f - zz) * nn + zz * hold;
                }
            *(__half2*)(d0n + gid * STR_D + j0) = __floats2half2_rn(val[0][0], val[0][1]);
            *(__half2*)(d0n + (gid + 8) * STR_D + j0) = __floats2half2_rn(val[1][0], val[1][1]);
        }
        __syncthreads();

        {
            float ai[3][4], ah[3][4];
            hgemm_reg<3, 8>(d0n, STR_D, g_wf_gi1, wid * 3, ai);
            hgemm_reg<3, 8>(d1p, STR_D, g_wf_gh1, wid * 3, ah);
            float val[2][2];
#pragma unroll
            for (int rs = 0; rs < 2; rs++)
#pragma unroll
                for (int e = 0; e < 2; e++) {
                    int ix = rs * 2 + e;
                    float rr = sigm(ai[0][ix] + ah[0][ix] + sgb1[j0 + e]);
                    float zz = sigm(ai[1][ix] + ah[1][ix] + sgb1[128 + j0 + e]);
                    float nn = fast_tanh(ai[2][ix] + sgb1[256 + j0 + e]
                                         + rr * (ah[2][ix] + sgb1[384 + j0 + e]));
                    float hold = __half2float(d1p[(gid + rs * 8) * STR_D + j0 + e]);
                    val[rs][e] = (1.f - zz) * nn + zz * hold;
                }
            *(__half2*)(d1n + gid * STR_D + j0) = __floats2half2_rn(val[0][0], val[0][1]);
            *(__half2*)(d1n + (gid + 8) * STR_D + j0) = __floats2half2_rn(val[1][0], val[1][1]);
        }
        __syncthreads();

        // barrier-free head: warp w owns row w
        {
            const __half* drow = d1n + wid * STR_D;
            float a0 = fcw2[128 + 2 * lane];
            float a1 = fcw2[128 + 2 * lane + 1];
#pragma unroll 4
            for (int k = 0; k < 128; k += 2) {
                float2 f = __half22float2(*(const __half2*)(drow + k));
                float2 w0 = *(const float2*)(gbuf + k * 64 + 2 * lane);
                float2 w1 = *(const float2*)(gbuf + (k + 1) * 64 + 2 * lane);
                a0 = fmaf(f.x, w0.x, a0); a0 = fmaf(f.y, w1.x, a0);
                a1 = fmaf(f.x, w0.y, a1); a1 = fmaf(f.y, w1.y, a1);
            }
            a0 = fmaxf(a0, 0.f); a1 = fmaxf(a1, 0.f);
            float s0 = a0 * fcw2[2 * lane]      + a1 * fcw2[2 * lane + 1];
            float s1 = a0 * fcw2[64 + 2 * lane] + a1 * fcw2[64 + 2 * lane + 1];
#pragma unroll
            for (int off = 16; off; off >>= 1) {
                s0 += __shfl_xor_sync(0xFFFFFFFFu, s0, off);
                s1 += __shfl_xor_sync(0xFFFFFFFFu, s1, off);
            }
            if (lane == 0) {
                float* op = out + (size_t)(b0 + wid) * PRED * 2 + t * 2;
                op[0] = s0 + fc2b[0];
                op[1] = s1 + fc2b[1];
            }
        }
    }
}

extern "C" void kernel_launch(void* const* d_in, const int* in_sizes, int n_in,
                              void* d_out, int out_size)
{
    const float* p[24];
    int np = 0;
    for (int i = 0; i < n_in && np < 24; i++) {
        if (in_sizes[i] == 1) continue;
        p[np++] = (const float*)d_in[i];
    }
    const float* x = p[0];
    const float *lwih0 = p[1], *lwhh0 = p[2], *lbih0 = p[3], *lbhh0 = p[4];
    const float *lwih1 = p[5], *lwhh1 = p[6], *lbih1 = p[7], *lbhh1 = p[8];
    const float *gwi0 = p[9], *gwh0 = p[10], *gbi0 = p[11], *gbh0 = p[12];
    const float *gwi1 = p[13], *gwh1 = p[14], *gbi1 = p[15], *gbh1 = p[16];
    const float *brw = p[17], *brb = p[18];
    const float *fc1w = p[19], *fc1b = p[20];
    const float *fc2w = p[21], *fc2b = p[22];

    prep_kernel<<<512, 256>>>(lwih0, lwhh0, lbih0, lbhh0, lwih1, lwhh1, lbih1, lbhh1,
                              gwi0, gwh0, gbi0, gbh0, gwi1, gwh1, gbi1, gbh1,
                              brw, fc1w);

    const int smem = 114688;
    cudaFuncSetAttribute(rnn_kernel, cudaFuncAttributeMaxDynamicSharedMemorySize, smem);
    rnn_kernel<<<NBLK, NTHR, smem>>>(x, brb, fc1b, fc2w, fc2b, (float*)d_out);
}